// round 13
// baseline (speedup 1.0000x reference)
#include <cuda_runtime.h>
#include <cuda_fp16.h>
#include <cstdint>

#define BATCH 4
#define SEQ   1024
#define NT    4096
#define DM    1024
#define NH    16
#define DKH   64
#define DFF   4096

// ======================= device scratch =======================
__device__ __align__(16) float g_tmp[(size_t)NT * DM];
__device__ __align__(16) float g_h[(size_t)NT * DM];
__device__ __align__(16) __half g_xh [(size_t)NT * DM];
__device__ __align__(16) __half g_qkv[(size_t)NT * 3 * DM];
__device__ __align__(16) __half g_ctx[(size_t)NT * DM];
__device__ __align__(16) __half g_WqkvT[(size_t)3 * DM * DM];
__device__ __align__(16) __half g_WoT[(size_t)DM * DM];
__device__ __align__(16) __half g_W1T[(size_t)DFF * DM];
__device__ __align__(16) __half g_W2T[(size_t)DM * DFF];
__device__ __align__(16) __half g_hh [(size_t)NT * DM];
__device__ __align__(16) __half g_ff [(size_t)NT * DFF];
__device__ __align__(16) float  g_bqkv[3 * DM];

// ======================= asm helpers (compute_80-level only) =======================
__device__ __forceinline__ uint32_t smem_u32(const void* p) {
    uint32_t a;
    asm("{ .reg .u64 t; cvta.to.shared.u64 t, %1; cvt.u32.u64 %0, t; }" : "=r"(a) : "l"(p));
    return a;
}
#define CP_ASYNC(s, g) \
    asm volatile("cp.async.cg.shared.global [%0], [%1], 16;" :: "r"(s), "l"(g) : "memory")
#define CP_COMMIT() asm volatile("cp.async.commit_group;" ::: "memory")
#define CP_WAIT(n)  asm volatile("cp.async.wait_group %0;" :: "n"(n) : "memory")

#define LDSM_X4(r0, r1, r2, r3, a) \
    asm volatile("ldmatrix.sync.aligned.m8n8.x4.shared.b16 {%0,%1,%2,%3}, [%4];" \
        : "=r"(r0), "=r"(r1), "=r"(r2), "=r"(r3) : "r"(a))

#define LDSM_X4_T(r0, r1, r2, r3, a) \
    asm volatile("ldmatrix.sync.aligned.m8n8.x4.trans.shared.b16 {%0,%1,%2,%3}, [%4];" \
        : "=r"(r0), "=r"(r1), "=r"(r2), "=r"(r3) : "r"(a))

#define MMA_F16(d, a, b) \
    asm volatile("mma.sync.aligned.m16n8k16.row.col.f32.f16.f16.f32 " \
        "{%0,%1,%2,%3}, {%4,%5,%6,%7}, {%8,%9}, {%0,%1,%2,%3};" \
        : "+f"((d)[0]), "+f"((d)[1]), "+f"((d)[2]), "+f"((d)[3]) \
        : "r"((a)[0]), "r"((a)[1]), "r"((a)[2]), "r"((a)[3]), "r"((b)[0]), "r"((b)[1]))

#define PACK_F16X2(r, flo, fhi) \
    asm("cvt.rn.f16x2.f32 %0, %1, %2;" : "=r"(r) : "f"(fhi), "f"(flo))

// 64B-row swizzle (flash): phys(r+16,c)==phys(r,c)+1024.
__device__ __forceinline__ uint32_t phys(uint32_t r, uint32_t c) {
    return (r >> 1) * 128 + ((((r & 1) << 2) | c) ^ ((r >> 1) & 7)) * 16;
}
// 128B-row swizzle (GEMM).
__device__ __forceinline__ uint32_t phys128(uint32_t r, uint32_t c) {
    return r * 128 + ((c ^ (r & 7)) * 16);
}
__device__ __forceinline__ unsigned short hfu(float v) {
    return __half_as_ushort(__float2half_rn(v));
}

// ======================= mma.sync batched GEMM: BM=128, BN=128, BK=64, DEPTH=3 =======================
// C[M,N] = alpha*(A @ B^T) + bias (+R). A:[M,K] half, B:[N,K] half row-major. K%64==0.
// OUT: 0=f32, 1=half, 2=relu half, 3=f32 with fused residual add (C = R + acc*alpha + bias).
template<int OUT>
__global__ __launch_bounds__(256, 2)
void mma_gemm(const __half* __restrict__ A, const __half* __restrict__ B,
              const float* __restrict__ bias, const float* __restrict__ R,
              char* __restrict__ Cptr,
              int K, int lda, int ldb, int ldc, float alpha)
{
    constexpr int DEPTH  = 3;
    constexpr int ABYTES = 128 * 128;       // 16 KB
    constexpr int STAGE  = 2 * ABYTES;      // 32 KB
    constexpr int NTL    = 8;               // warp: 32 rows x 64 cols

    extern __shared__ char sm[];
    const uint32_t smb = smem_u32(sm);

    const int tid = threadIdx.x;
    const int wid = tid >> 5, lane = tid & 31;
    const int wRow = (wid & 3) * 32;
    const int wCol = (wid >> 2) * 64;
    const int row0 = blockIdx.y * 128;
    const int col0 = blockIdx.x * 128;

    const __half* Ag[4]; const __half* Bg[4]; uint32_t Asm[4], Bsm[4];
#pragma unroll
    for (int i = 0; i < 4; i++) {
        int idx = tid + i * 256;
        int r = idx >> 3, c = idx & 7;
        Ag[i]  = A + (size_t)(row0 + r) * lda + c * 8;
        Bg[i]  = B + (size_t)(col0 + r) * ldb + c * 8;
        Asm[i] = phys128(r, c);
        Bsm[i] = ABYTES + phys128(r, c);
    }

    const uint32_t ra0 = (uint32_t)(wRow + (lane & 15)) * 128;
    const uint32_t rmA = (uint32_t)(lane & 15) & 7;
    const uint32_t sA  = lane >> 4;
    const uint32_t rb0 = (uint32_t)(wCol + ((lane >> 4) << 3) + (lane & 7)) * 128;
    const uint32_t rmB = (uint32_t)lane & 7;
    const uint32_t sB  = (lane >> 3) & 1;

    float acc[2][NTL][4];
#pragma unroll
    for (int i = 0; i < 2; i++)
#pragma unroll
        for (int j = 0; j < NTL; j++)
#pragma unroll
            for (int k = 0; k < 4; k++) acc[i][j][k] = 0.f;

    const int NC = K / 64;
    const int PRE = NC < (DEPTH - 1) ? NC : (DEPTH - 1);
    for (int s = 0; s < PRE; s++) {
#pragma unroll
        for (int i = 0; i < 4; i++) {
            CP_ASYNC(smb + s * STAGE + Asm[i], Ag[i] + s * 64);
            CP_ASYNC(smb + s * STAGE + Bsm[i], Bg[i] + s * 64);
        }
        CP_COMMIT();
    }
    int idx = PRE;
    int stC = 0, stL = PRE % DEPTH;
    for (int cch = 0; cch < NC; cch++) {
        const int rem = NC - 1 - cch;
        if (rem >= 1) { CP_WAIT(1); } else { CP_WAIT(0); }
        __syncthreads();
        if (idx < NC) {
#pragma unroll
            for (int i = 0; i < 4; i++) {
                CP_ASYNC(smb + stL * STAGE + Asm[i], Ag[i] + idx * 64);
                CP_ASYNC(smb + stL * STAGE + Bsm[i], Bg[i] + idx * 64);
            }
            CP_COMMIT();
            idx++;
            stL = (stL + 1 == DEPTH) ? 0 : stL + 1;
        }
        const uint32_t sb = smb + stC * STAGE;
        stC = (stC + 1 == DEPTH) ? 0 : stC + 1;
#pragma unroll
        for (int kk = 0; kk < 4; kk++) {
            const uint32_t cA = ((2 * kk + sA) ^ rmA) * 16;
            const uint32_t cB = ((2 * kk + sB) ^ rmB) * 16;
            uint32_t a[2][4], b[NTL][2];
#pragma unroll
            for (int mt = 0; mt < 2; mt++)
                LDSM_X4(a[mt][0], a[mt][1], a[mt][2], a[mt][3],
                        sb + ra0 + mt * 2048 + cA);
#pragma unroll
            for (int np = 0; np < 4; np++)
                LDSM_X4(b[2 * np][0], b[2 * np][1], b[2 * np + 1][0], b[2 * np + 1][1],
                        sb + ABYTES + rb0 + np * 2048 + cB);
#pragma unroll
            for (int mt = 0; mt < 2; mt++)
#pragma unroll
                for (int nt = 0; nt < NTL; nt++)
                    MMA_F16(acc[mt][nt], a[mt], b[nt]);
        }
    }

    const int gid = lane >> 2, t4 = lane & 3;
#pragma unroll
    for (int mt = 0; mt < 2; mt++) {
        const int r1 = row0 + wRow + mt * 16 + gid;
        const long long ro1 = (long long)r1 * ldc;
        const long long ro2 = ro1 + 8LL * ldc;
#pragma unroll
        for (int nt = 0; nt < NTL; nt++) {
            const int cc = col0 + wCol + nt * 8 + t4 * 2;
            const float b0 = bias ? bias[cc] : 0.f;
            const float b1 = bias ? bias[cc + 1] : 0.f;
            float v0 = acc[mt][nt][0] * alpha + b0;
            float v1 = acc[mt][nt][1] * alpha + b1;
            float v2 = acc[mt][nt][2] * alpha + b0;
            float v3 = acc[mt][nt][3] * alpha + b1;
            if constexpr (OUT == 0 || OUT == 3) {
                float* C = (float*)Cptr;
                if constexpr (OUT == 3) {
                    float2 r1v = *(const float2*)(R + ro1 + cc);
                    float2 r2v = *(const float2*)(R + ro2 + cc);
                    v0 = r1v.x + v0; v1 = r1v.y + v1;
                    v2 = r2v.x + v2; v3 = r2v.y + v3;
                }
                *(float2*)(C + ro1 + cc) = make_float2(v0, v1);
                *(float2*)(C + ro2 + cc) = make_float2(v2, v3);
            } else {
                if constexpr (OUT == 2) {
                    v0 = fmaxf(v0, 0.f); v1 = fmaxf(v1, 0.f);
                    v2 = fmaxf(v2, 0.f); v3 = fmaxf(v3, 0.f);
                }
                __half* C = (__half*)Cptr;
                ushort2 o1, o2;
                o1.x = hfu(v0); o1.y = hfu(v1);
                o2.x = hfu(v2); o2.y = hfu(v3);
                *(ushort2*)(C + ro1 + cc) = o1;
                *(ushort2*)(C + ro2 + cc) = o2;
            }
        }
    }
}

// ======================= flash attention: no-max-tracking softmax =======================
__global__ __launch_bounds__(256, 2)
void flash_k(const __half* __restrict__ QKV, const int* __restrict__ mask,
             __half* __restrict__ CTX)
{
    constexpr int QLD   = 3 * DM;
    constexpr int CH128 = 8192;
    constexpr int CH64  = 4096;
    constexpr int QOFF  = 0;
    constexpr int ST0   = 16384;
    constexpr int VOFF  = 8192;
    constexpr int MOFF  = 16384;
    constexpr int STSZ  = 16640;
    constexpr int NJ    = SEQ / 64;
    constexpr float SCLL2E = 0.125f * 1.44269504f;

    extern __shared__ char sm[];
    const uint32_t smb = smem_u32(sm);

    const int tid = threadIdx.x;
    const int wid = tid >> 5, lane = tid & 31;
    const int gid = lane >> 2, t4 = lane & 3;
    const int qb = blockIdx.x, z = blockIdx.y;
    const int b = z >> 4, h = z & 15;

    const int rr = tid >> 2, cc4 = tid & 3;
    const size_t qrow0 = (size_t)(b * SEQ + qb * 128);
    const __half* Qg  = QKV + (qrow0 + rr) * QLD + h * DKH + cc4 * 8;
    const __half* Kg0 = QKV + ((size_t)b * SEQ + rr) * QLD + DM + h * DKH + cc4 * 8;
    const __half* Vg0 = QKV + ((size_t)b * SEQ + rr) * QLD + 2 * DM + h * DKH + cc4 * 8;
    const uint32_t physrc = phys(rr, cc4);

    auto issue_stage = [&](int jb, int st) {
        const uint32_t sb = smb + ST0 + st * STSZ;
        const __half* kgb = Kg0 + (size_t)jb * 64 * QLD;
#pragma unroll
        for (int kc = 0; kc < 2; kc++)
            CP_ASYNC(sb + kc * CH64 + physrc, kgb + kc * 32);
        const __half* vgb = Vg0 + (size_t)jb * 64 * QLD;
#pragma unroll
        for (int kc = 0; kc < 2; kc++)
            CP_ASYNC(sb + VOFF + kc * CH64 + physrc, vgb + kc * 32);
        if (tid < 16)
            CP_ASYNC(sb + MOFF + tid * 16, mask + (size_t)b * SEQ + jb * 64 + tid * 4);
    };

#pragma unroll
    for (int kc = 0; kc < 2; kc++)
#pragma unroll
        for (int it = 0; it < 2; it++)
            CP_ASYNC(smb + QOFF + kc * CH128 + physrc + it * 32 * 128,
                     Qg + (size_t)it * 64 * QLD + kc * 32);
    issue_stage(0, 0);
    CP_COMMIT();
    issue_stage(1, 1);
    CP_COMMIT();
    CP_WAIT(1);
    __syncthreads();

    uint32_t qa[4][4];
    {
        const uint32_t qbase0 = phys(lane & 15, (lane >> 4)) + wid * 1024;
        const uint32_t qbase1 = phys(lane & 15, 2 + (lane >> 4)) + wid * 1024;
#pragma unroll
        for (int kc = 0; kc < 2; kc++) {
            LDSM_X4(qa[kc * 2][0], qa[kc * 2][1], qa[kc * 2][2], qa[kc * 2][3],
                    smb + QOFF + kc * CH128 + qbase0);
            LDSM_X4(qa[kc * 2 + 1][0], qa[kc * 2 + 1][1], qa[kc * 2 + 1][2], qa[kc * 2 + 1][3],
                    smb + QOFF + kc * CH128 + qbase1);
        }
    }

    const uint32_t bb0 = phys(((lane >> 4) << 3) + (lane & 7), ((lane >> 3) & 1));
    const uint32_t bb1 = phys(((lane >> 4) << 3) + (lane & 7), 2 + ((lane >> 3) & 1));
    const uint32_t vtb0 = phys(lane & 15, (lane >> 4));
    const uint32_t vtb1 = phys(lane & 15, 2 + (lane >> 4));

    float O[8][4];
#pragma unroll
    for (int i = 0; i < 8; i++)
#pragma unroll
        for (int j = 0; j < 4; j++) O[i][j] = 0.f;
    float l0 = 0.f, l1 = 0.f;

    for (int j = 0; j < NJ; j++) {
        const uint32_t sb = smb + ST0 + (j & 1) * STSZ;
        const int* msm = (const int*)(sm + ST0 + (j & 1) * STSZ + MOFF);

        float s[8][4];
#pragma unroll
        for (int i = 0; i < 8; i++)
#pragma unroll
            for (int k = 0; k < 4; k++) s[i][k] = 0.f;
#pragma unroll
        for (int kidx = 0; kidx < 4; kidx++) {
            const uint32_t cb = sb + (kidx >> 1) * CH64 + ((kidx & 1) ? bb1 : bb0);
#pragma unroll
            for (int np = 0; np < 4; np++) {
                uint32_t r0, r1, r2, r3;
                LDSM_X4(r0, r1, r2, r3, cb + np * 1024);
                uint32_t p0[2] = {r0, r1}, p1[2] = {r2, r3};
                MMA_F16(s[2 * np], qa[kidx], p0);
                MMA_F16(s[2 * np + 1], qa[kidx], p1);
            }
        }

        float sum0 = 0.f, sum1 = 0.f;
#pragma unroll
        for (int nt = 0; nt < 8; nt++) {
            const int c0 = nt * 8 + t4 * 2;
            const float a0 = msm[c0] ? 0.f : -1.0e9f;
            const float a1 = msm[c0 + 1] ? 0.f : -1.0e9f;
            s[nt][0] = exp2f(fmaf(s[nt][0], SCLL2E, a0));
            s[nt][1] = exp2f(fmaf(s[nt][1], SCLL2E, a1));
            s[nt][2] = exp2f(fmaf(s[nt][2], SCLL2E, a0));
            s[nt][3] = exp2f(fmaf(s[nt][3], SCLL2E, a1));
            sum0 += s[nt][0] + s[nt][1];
            sum1 += s[nt][2] + s[nt][3];
        }
        sum0 += __shfl_xor_sync(0xffffffffu, sum0, 1);
        sum0 += __shfl_xor_sync(0xffffffffu, sum0, 2);
        sum1 += __shfl_xor_sync(0xffffffffu, sum1, 1);
        sum1 += __shfl_xor_sync(0xffffffffu, sum1, 2);
        l0 += sum0;
        l1 += sum1;

#pragma unroll
        for (int kt = 0; kt < 4; kt++) {
            uint32_t pa[4];
            PACK_F16X2(pa[0], s[2 * kt][0], s[2 * kt][1]);
            PACK_F16X2(pa[1], s[2 * kt][2], s[2 * kt][3]);
            PACK_F16X2(pa[2], s[2 * kt + 1][0], s[2 * kt + 1][1]);
            PACK_F16X2(pa[3], s[2 * kt + 1][2], s[2 * kt + 1][3]);
#pragma unroll
            for (int np = 0; np < 4; np++) {
                uint32_t r0, r1, r2, r3;
                LDSM_X4_T(r0, r1, r2, r3,
                          sb + VOFF + (np >> 1) * CH64 + ((np & 1) ? vtb1 : vtb0) + kt * 1024);
                uint32_t p0[2] = {r0, r1}, p1[2] = {r2, r3};
                MMA_F16(O[2 * np], pa, p0);
                MMA_F16(O[2 * np + 1], pa, p1);
            }
        }

        __syncthreads();
        if (j + 2 < NJ) { issue_stage(j + 2, j & 1); CP_COMMIT(); CP_WAIT(1); }
        else if (j + 1 < NJ) { CP_WAIT(0); }
        __syncthreads();
    }

    const float inv0 = 1.f / l0, inv1 = 1.f / l1;
    const int q0 = qb * 128 + wid * 16 + gid;
    __half* C1 = CTX + ((size_t)(b * SEQ + q0)) * DM + h * DKH;
    __half* C2 = C1 + 8 * DM;
#pragma unroll
    for (int nt = 0; nt < 8; nt++) {
        const int cc = nt * 8 + t4 * 2;
        ushort2 o1, o2;
        o1.x = hfu(O[nt][0] * inv0); o1.y = hfu(O[nt][1] * inv0);
        o2.x = hfu(O[nt][2] * inv1); o2.y = hfu(O[nt][3] * inv1);
        *(ushort2*)(C1 + cc) = o1;
        *(ushort2*)(C2 + cc) = o2;
    }
}

// ======================= prologue kernels =======================
__global__ void f32_to_half_k(const float* __restrict__ in, __half* __restrict__ out, int n4)
{
    int i = blockIdx.x * 256 + threadIdx.x;
    if (i < n4) {
        float4 v = *(const float4*)(in + (size_t)i * 4);
        ushort4 o;
        o.x = hfu(v.x); o.y = hfu(v.y); o.z = hfu(v.z); o.w = hfu(v.w);
        *(ushort4*)(out + (size_t)i * 4) = o;
    }
}

__global__ void prep_w_k(const float* __restrict__ Wq, const float* __restrict__ Wk,
                         const float* __restrict__ Wv, const float* __restrict__ Wo,
                         const float* __restrict__ W1, const float* __restrict__ W2,
                         __half* __restrict__ WQKVT, __half* __restrict__ WOT,
                         __half* __restrict__ W1T, __half* __restrict__ W2T,
                         const float* __restrict__ bq, const float* __restrict__ bk,
                         const float* __restrict__ bv, float* __restrict__ BQKV, int base)
{
    __shared__ float t[32][33];
    const int idx = base + blockIdx.x;
    const int tx = threadIdx.x, ty = threadIdx.y;
    const int lt = ty * 32 + tx;

    if (idx == 0) {
        for (int i = lt; i < DM; i += 256) {
            BQKV[i] = bq[i];
            BQKV[i + DM] = bk[i];
            BQKV[i + 2 * DM] = bv[i];
        }
    }

    const float* in;
    __half* out;
    int K, N, n0, k0;
    if (idx < 4096) {
        const int w = idx >> 10, tile = idx & 1023;
        in = (w == 0) ? Wq : (w == 1) ? Wk : (w == 2) ? Wv : Wo;
        out = (w == 3) ? WOT : WQKVT + (size_t)w * DM * DM;
        K = DM; N = DM;
        n0 = (tile & 31) * 32; k0 = (tile >> 5) * 32;
    } else if (idx < 8192) {
        const int tile = idx - 4096;
        in = W1; out = W1T; K = DM; N = DFF;
        n0 = (tile & 127) * 32; k0 = (tile >> 7) * 32;
    } else {
        const int tile = idx - 8192;
        in = W2; out = W2T; K = DFF; N = DM;
        n0 = (tile & 31) * 32; k0 = (tile >> 5) * 32;
    }

    for (int j = ty; j < 32; j += 8) t[j][tx] = in[(size_t)(k0 + j) * N + n0 + tx];
    __syncthreads();
    for (int j = ty; j < 32; j += 8)
        out[(size_t)(n0 + j) * K + k0 + tx] = __float2half_rn(t[tx][j]);
}

// ======================= reductions / LN =======================
__device__ __forceinline__ float blkSum(float v, float* red)
{
#pragma unroll
    for (int o = 16; o > 0; o >>= 1) v += __shfl_xor_sync(0xffffffffu, v, o);
    int w = threadIdx.x >> 5, l = threadIdx.x & 31;
    if (l == 0) red[w] = v;
    __syncthreads();
    if (threadIdx.x < 8) {
        v = red[threadIdx.x];
#pragma unroll
        for (int o = 4; o > 0; o >>= 1) v += __shfl_xor_sync(0xffu, v, o);
        if (threadIdx.x == 0) red[0] = v;
    }
    __syncthreads();
    float r = red[0];
    __syncthreads();
    return r;
}

// out = LN(t)*g+be, single input (residual pre-added in GEMM epilogue).
template<bool EMIT_H>
__global__ void ln_k(const float* __restrict__ t, const float* __restrict__ g,
                     const float* __restrict__ be, float* __restrict__ out,
                     __half* __restrict__ outh)
{
    __shared__ float red[32];
    const long long row = blockIdx.x;
    const float* pt = t + row * DM;
    const int tid = threadIdx.x;
    float v[4], s = 0.f, s2 = 0.f;
    {
        float4 x = *(const float4*)(pt + tid * 4);
        v[0] = x.x; v[1] = x.y; v[2] = x.z; v[3] = x.w;
#pragma unroll
        for (int j = 0; j < 4; j++) { s += v[j]; s2 += v[j] * v[j]; }
    }
    s = blkSum(s, red);
    s2 = blkSum(s2, red);
    float mu = s * (1.f / DM);
    float var = s2 * (1.f / DM) - mu * mu;
    float inv = rsqrtf(var + 1e-5f);
    float4 gv = *(const float4*)(g + tid * 4);
    float4 bv = *(const float4*)(be + tid * 4);
    float o0 = (v[0] - mu) * inv * gv.x + bv.x;
    float o1 = (v[1] - mu) * inv * gv.y + bv.y;
    float o2 = (v[2] - mu) * inv * gv.z + bv.z;
    float o3 = (v[3] - mu) * inv * gv.w + bv.w;
    *(float4*)(out + row * DM + tid * 4) = make_float4(o0, o1, o2, o3);
    if (EMIT_H) {
        ushort4 oh;
        oh.x = hfu(o0); oh.y = hfu(o1); oh.z = hfu(o2); oh.w = hfu(o3);
        *(ushort4*)(outh + row * DM + tid * 4) = oh;
    }
}

// ======================= launch =======================
extern "C" void kernel_launch(void* const* d_in, const int* in_sizes, int n_in,
                              void* d_out, int out_size)
{
    const float* x    = (const float*)d_in[0];
    const int*   mask = (const int*)  d_in[1];
    const float* Wq = (const float*)d_in[2];  const float* bq = (const float*)d_in[3];
    const float* Wk = (const float*)d_in[4];  const float* bk = (const float*)d_in[5];
    const float* Wv = (const float*)d_in[6];  const float* bv = (const float*)d_in[7];
    const float* Wo = (const float*)d_in[8];  const float* bo = (const float*)d_in[9];
    const float* W1 = (const float*)d_in[10]; const float* b1 = (const float*)d_in[11];
    const float* W2 = (const float*)d_in[12]; const float* b2 = (const float*)d_in[13];
    const float* g1 = (const float*)d_in[14]; const float* be1 = (const float*)d_in[15];
    const float* g2 = (const float*)d_in[16]; const float* be2 = (const float*)d_in[17];
    float* out = (float*)d_out;

    float *TMP, *H, *BQKV;
    __half *XH, *QKV, *CTX, *WQKVT, *WOT, *W1T, *W2T, *HH, *FF;
    cudaGetSymbolAddress((void**)&TMP, g_tmp);
    cudaGetSymbolAddress((void**)&H, g_h);
    cudaGetSymbolAddress((void**)&XH, g_xh);
    cudaGetSymbolAddress((void**)&QKV, g_qkv);
    cudaGetSymbolAddress((void**)&CTX, g_ctx);
    cudaGetSymbolAddress((void**)&WQKVT, g_WqkvT);
    cudaGetSymbolAddress((void**)&WOT, g_WoT);
    cudaGetSymbolAddress((void**)&W1T, g_W1T);
    cudaGetSymbolAddress((void**)&W2T, g_W2T);
    cudaGetSymbolAddress((void**)&HH, g_hh);
    cudaGetSymbolAddress((void**)&FF, g_ff);
    cudaGetSymbolAddress((void**)&BQKV, g_bqkv);

    const int SMGM = 3 * 32 * 1024;           // 98304
    const int SMFL = 16384 + 2 * 16640;       // 49664
    cudaFuncSetAttribute(mma_gemm<1>, cudaFuncAttributeMaxDynamicSharedMemorySize, SMGM);
    cudaFuncSetAttribute(mma_gemm<2>, cudaFuncAttributeMaxDynamicSharedMemorySize, SMGM);
    cudaFuncSetAttribute(mma_gemm<3>, cudaFuncAttributeMaxDynamicSharedMemorySize, SMGM);
    cudaFuncSetAttribute(flash_k, cudaFuncAttributeMaxDynamicSharedMemorySize, SMFL);

    const dim3 t32(32, 8);

    // launch 1: x -> half
    f32_to_half_k<<<(NT * DM / 4 + 255) / 256, 256>>>(x, XH, NT * DM / 4);
    // launch 2: Wq/Wk/Wv transposes + bias concat
    prep_w_k<<<3072, t32>>>(Wq, Wk, Wv, Wo, W1, W2, WQKVT, WOT, W1T, W2T, bq, bk, bv, BQKV, 0);
    // launch 3: Wo/W1/W2 transposes
    prep_w_k<<<9216, t32>>>(Wq, Wk, Wv, Wo, W1, W2, WQKVT, WOT, W1T, W2T, bq, bk, bv, BQKV, 3072);
    // launch 4: fused QKV projection
    {
        dim3 g(3 * DM / 128, NT / 128, 1);
        mma_gemm<1><<<g, 256, SMGM>>>(XH, WQKVT, BQKV, nullptr, (char*)QKV, DM, DM, DM, 3 * DM, 1.f);
    }
    // launch 5: flash attention
    flash_k<<<dim3(SEQ / 128, 64), 256, SMFL>>>(QKV, mask, CTX);
    // launch 6: TMP = x + ctx @ Wo + bo  (residual fused)
    {
        dim3 g(DM / 128, NT / 128, 1);
        mma_gemm<3><<<g, 256, SMGM>>>(CTX, WOT, bo, x, (char*)TMP, DM, DM, DM, DM, 1.f);
    }
    // launch 7: H,HH = LN1(TMP)
    ln_k<true><<<NT, 256>>>(TMP, g1, be1, H, HH);
    // launch 8: FF = relu(HH @ W1 + b1)
    {
        dim3 g(DFF / 128, NT / 128, 1);
        mma_gemm<2><<<g, 256, SMGM>>>(HH, W1T, b1, nullptr, (char*)FF, DM, DM, DM, DFF, 1.f);
    }
    // launch 9: TMP = H + FF @ W2 + b2  (residual fused)
    {
        dim3 g(DM / 128, NT / 128, 1);
        mma_gemm<3><<<g, 256, SMGM>>>(FF, W2T, b2, H, (char*)TMP, DFF, DFF, DFF, DM, 1.f);
    }
    // launch 10: out = LN2(TMP)
    ln_k<false><<<NT, 256>>>(TMP, g2, be2, out, nullptr);
}

// round 14
// speedup vs baseline: 1.0002x; 1.0002x over previous
#include <cuda_runtime.h>
#include <cuda_fp16.h>
#include <cstdint>

#define BATCH 4
#define SEQ   1024
#define NT    4096
#define DM    1024
#define NH    16
#define DKH   64
#define DFF   4096

// ======================= device scratch =======================
__device__ __align__(16) float g_tmp[(size_t)NT * DM];
__device__ __align__(16) float g_h[(size_t)NT * DM];
__device__ __align__(16) __half g_xh [(size_t)NT * DM];
__device__ __align__(16) __half g_qkv[(size_t)NT * 3 * DM];
__device__ __align__(16) __half g_ctx[(size_t)NT * DM];
__device__ __align__(16) __half g_WqkvT[(size_t)3 * DM * DM];
__device__ __align__(16) __half g_WoT[(size_t)DM * DM];
__device__ __align__(16) __half g_W1T[(size_t)DFF * DM];
__device__ __align__(16) __half g_W2T[(size_t)DM * DFF];
__device__ __align__(16) __half g_hh [(size_t)NT * DM];
__device__ __align__(16) __half g_ff [(size_t)NT * DFF];
__device__ __align__(16) float  g_bqkv[3 * DM];

// ======================= asm helpers (compute_80-level only) =======================
__device__ __forceinline__ uint32_t smem_u32(const void* p) {
    uint32_t a;
    asm("{ .reg .u64 t; cvta.to.shared.u64 t, %1; cvt.u32.u64 %0, t; }" : "=r"(a) : "l"(p));
    return a;
}
#define CP_ASYNC(s, g) \
    asm volatile("cp.async.cg.shared.global [%0], [%1], 16;" :: "r"(s), "l"(g) : "memory")
#define CP_COMMIT() asm volatile("cp.async.commit_group;" ::: "memory")
#define CP_WAIT(n)  asm volatile("cp.async.wait_group %0;" :: "n"(n) : "memory")

#define LDSM_X4(r0, r1, r2, r3, a) \
    asm volatile("ldmatrix.sync.aligned.m8n8.x4.shared.b16 {%0,%1,%2,%3}, [%4];" \
        : "=r"(r0), "=r"(r1), "=r"(r2), "=r"(r3) : "r"(a))

#define LDSM_X4_T(r0, r1, r2, r3, a) \
    asm volatile("ldmatrix.sync.aligned.m8n8.x4.trans.shared.b16 {%0,%1,%2,%3}, [%4];" \
        : "=r"(r0), "=r"(r1), "=r"(r2), "=r"(r3) : "r"(a))

#define MMA_F16(d, a, b) \
    asm volatile("mma.sync.aligned.m16n8k16.row.col.f32.f16.f16.f32 " \
        "{%0,%1,%2,%3}, {%4,%5,%6,%7}, {%8,%9}, {%0,%1,%2,%3};" \
        : "+f"((d)[0]), "+f"((d)[1]), "+f"((d)[2]), "+f"((d)[3]) \
        : "r"((a)[0]), "r"((a)[1]), "r"((a)[2]), "r"((a)[3]), "r"((b)[0]), "r"((b)[1]))

// f16-accumulate variant: 2 packed-half2 accumulator regs.
#define MMA_F16H(d, a, b) \
    asm volatile("mma.sync.aligned.m16n8k16.row.col.f16.f16.f16.f16 " \
        "{%0,%1}, {%2,%3,%4,%5}, {%6,%7}, {%0,%1};" \
        : "+r"((d)[0]), "+r"((d)[1]) \
        : "r"((a)[0]), "r"((a)[1]), "r"((a)[2]), "r"((a)[3]), "r"((b)[0]), "r"((b)[1]))

#define PACK_F16X2(r, flo, fhi) \
    asm("cvt.rn.f16x2.f32 %0, %1, %2;" : "=r"(r) : "f"(fhi), "f"(flo))

// 64B-row swizzle (flash): phys(r+16,c)==phys(r,c)+1024.
__device__ __forceinline__ uint32_t phys(uint32_t r, uint32_t c) {
    return (r >> 1) * 128 + ((((r & 1) << 2) | c) ^ ((r >> 1) & 7)) * 16;
}
// 128B-row swizzle (GEMM).
__device__ __forceinline__ uint32_t phys128(uint32_t r, uint32_t c) {
    return r * 128 + ((c ^ (r & 7)) * 16);
}
__device__ __forceinline__ unsigned short hfu(float v) {
    return __half_as_ushort(__float2half_rn(v));
}

// ======================= mma.sync batched GEMM: BM=128, BN=128, BK=64, DEPTH=3 =======================
// C[M,N] = alpha*(A @ B^T) + bias. A:[M,K] half, B:[N,K] half row-major. K%64==0.
// OUT: 0=f32, 1=half, 2=relu half.  HACC: 1 = f16 accumulators (attention branch only).
template<int OUT, int HACC>
__global__ __launch_bounds__(256, 2)
void mma_gemm(const __half* __restrict__ A, const __half* __restrict__ B,
              const float* __restrict__ bias, char* __restrict__ Cptr,
              int K, int lda, int ldb, int ldc, float alpha)
{
    constexpr int DEPTH  = 3;
    constexpr int ABYTES = 128 * 128;       // 16 KB
    constexpr int STAGE  = 2 * ABYTES;      // 32 KB
    constexpr int NTL    = 8;               // warp: 32 rows x 64 cols

    extern __shared__ char sm[];
    const uint32_t smb = smem_u32(sm);

    const int tid = threadIdx.x;
    const int wid = tid >> 5, lane = tid & 31;
    const int wRow = (wid & 3) * 32;
    const int wCol = (wid >> 2) * 64;
    const int row0 = blockIdx.y * 128;
    const int col0 = blockIdx.x * 128;

    const __half* Ag[4]; const __half* Bg[4]; uint32_t Asm[4], Bsm[4];
#pragma unroll
    for (int i = 0; i < 4; i++) {
        int idx = tid + i * 256;
        int r = idx >> 3, c = idx & 7;
        Ag[i]  = A + (size_t)(row0 + r) * lda + c * 8;
        Bg[i]  = B + (size_t)(col0 + r) * ldb + c * 8;
        Asm[i] = phys128(r, c);
        Bsm[i] = ABYTES + phys128(r, c);
    }

    const uint32_t ra0 = (uint32_t)(wRow + (lane & 15)) * 128;
    const uint32_t rmA = (uint32_t)(lane & 15) & 7;
    const uint32_t sA  = lane >> 4;
    const uint32_t rb0 = (uint32_t)(wCol + ((lane >> 4) << 3) + (lane & 7)) * 128;
    const uint32_t rmB = (uint32_t)lane & 7;
    const uint32_t sB  = (lane >> 3) & 1;

    float acc[2][HACC ? 1 : NTL][4];
    uint32_t hacc[2][HACC ? NTL : 1][2];
    if constexpr (HACC) {
#pragma unroll
        for (int i = 0; i < 2; i++)
#pragma unroll
            for (int j = 0; j < NTL; j++) { hacc[i][j][0] = 0u; hacc[i][j][1] = 0u; }
    } else {
#pragma unroll
        for (int i = 0; i < 2; i++)
#pragma unroll
            for (int j = 0; j < NTL; j++)
#pragma unroll
                for (int k = 0; k < 4; k++) acc[i][j][k] = 0.f;
    }

    const int NC = K / 64;
    const int PRE = NC < (DEPTH - 1) ? NC : (DEPTH - 1);
    for (int s = 0; s < PRE; s++) {
#pragma unroll
        for (int i = 0; i < 4; i++) {
            CP_ASYNC(smb + s * STAGE + Asm[i], Ag[i] + s * 64);
            CP_ASYNC(smb + s * STAGE + Bsm[i], Bg[i] + s * 64);
        }
        CP_COMMIT();
    }
    int idx = PRE;
    int stC = 0, stL = PRE % DEPTH;
    for (int cch = 0; cch < NC; cch++) {
        const int rem = NC - 1 - cch;
        if (rem >= 1) { CP_WAIT(1); } else { CP_WAIT(0); }
        __syncthreads();
        if (idx < NC) {
#pragma unroll
            for (int i = 0; i < 4; i++) {
                CP_ASYNC(smb + stL * STAGE + Asm[i], Ag[i] + idx * 64);
                CP_ASYNC(smb + stL * STAGE + Bsm[i], Bg[i] + idx * 64);
            }
            CP_COMMIT();
            idx++;
            stL = (stL + 1 == DEPTH) ? 0 : stL + 1;
        }
        const uint32_t sb = smb + stC * STAGE;
        stC = (stC + 1 == DEPTH) ? 0 : stC + 1;
#pragma unroll
        for (int kk = 0; kk < 4; kk++) {
            const uint32_t cA = ((2 * kk + sA) ^ rmA) * 16;
            const uint32_t cB = ((2 * kk + sB) ^ rmB) * 16;
            uint32_t a[2][4], b[NTL][2];
#pragma unroll
            for (int mt = 0; mt < 2; mt++)
                LDSM_X4(a[mt][0], a[mt][1], a[mt][2], a[mt][3],
                        sb + ra0 + mt * 2048 + cA);
#pragma unroll
            for (int np = 0; np < 4; np++)
                LDSM_X4(b[2 * np][0], b[2 * np][1], b[2 * np + 1][0], b[2 * np + 1][1],
                        sb + ABYTES + rb0 + np * 2048 + cB);
#pragma unroll
            for (int mt = 0; mt < 2; mt++)
#pragma unroll
                for (int nt = 0; nt < NTL; nt++) {
                    if constexpr (HACC) MMA_F16H(hacc[mt][nt], a[mt], b[nt]);
                    else                MMA_F16(acc[mt][nt], a[mt], b[nt]);
                }
        }
    }

    const int gid = lane >> 2, t4 = lane & 3;
#pragma unroll
    for (int mt = 0; mt < 2; mt++) {
        const int r1 = row0 + wRow + mt * 16 + gid;
        const long long ro1 = (long long)r1 * ldc;
        const long long ro2 = ro1 + 8LL * ldc;
#pragma unroll
        for (int nt = 0; nt < NTL; nt++) {
            const int cc = col0 + wCol + nt * 8 + t4 * 2;
            const float b0 = bias ? bias[cc] : 0.f;
            const float b1 = bias ? bias[cc + 1] : 0.f;
            float d0, d1, d2, d3;
            if constexpr (HACC) {
                __half2 p0 = *(__half2*)&hacc[mt][nt][0];
                __half2 p1 = *(__half2*)&hacc[mt][nt][1];
                d0 = __low2float(p0); d1 = __high2float(p0);
                d2 = __low2float(p1); d3 = __high2float(p1);
            } else {
                d0 = acc[mt][nt][0]; d1 = acc[mt][nt][1];
                d2 = acc[mt][nt][2]; d3 = acc[mt][nt][3];
            }
            float v0 = d0 * alpha + b0;
            float v1 = d1 * alpha + b1;
            float v2 = d2 * alpha + b0;
            float v3 = d3 * alpha + b1;
            if constexpr (OUT == 0) {
                float* C = (float*)Cptr;
                *(float2*)(C + ro1 + cc) = make_float2(v0, v1);
                *(float2*)(C + ro2 + cc) = make_float2(v2, v3);
            } else {
                if constexpr (OUT == 2) {
                    v0 = fmaxf(v0, 0.f); v1 = fmaxf(v1, 0.f);
                    v2 = fmaxf(v2, 0.f); v3 = fmaxf(v3, 0.f);
                }
                __half* C = (__half*)Cptr;
                ushort2 o1, o2;
                o1.x = hfu(v0); o1.y = hfu(v1);
                o2.x = hfu(v2); o2.y = hfu(v3);
                *(ushort2*)(C + ro1 + cc) = o1;
                *(ushort2*)(C + ro2 + cc) = o2;
            }
        }
    }
}

// ======================= flash attention: no-max-tracking softmax =======================
__global__ __launch_bounds__(256, 2)
void flash_k(const __half* __restrict__ QKV, const int* __restrict__ mask,
             __half* __restrict__ CTX)
{
    constexpr int QLD   = 3 * DM;
    constexpr int CH128 = 8192;
    constexpr int CH64  = 4096;
    constexpr int QOFF  = 0;
    constexpr int ST0   = 16384;
    constexpr int VOFF  = 8192;
    constexpr int MOFF  = 16384;
    constexpr int STSZ  = 16640;
    constexpr int NJ    = SEQ / 64;
    constexpr float SCLL2E = 0.125f * 1.44269504f;

    extern __shared__ char sm[];
    const uint32_t smb = smem_u32(sm);

    const int tid = threadIdx.x;
    const int wid = tid >> 5, lane = tid & 31;
    const int gid = lane >> 2, t4 = lane & 3;
    const int qb = blockIdx.x, z = blockIdx.y;
    const int b = z >> 4, h = z & 15;

    const int rr = tid >> 2, cc4 = tid & 3;
    const size_t qrow0 = (size_t)(b * SEQ + qb * 128);
    const __half* Qg  = QKV + (qrow0 + rr) * QLD + h * DKH + cc4 * 8;
    const __half* Kg0 = QKV + ((size_t)b * SEQ + rr) * QLD + DM + h * DKH + cc4 * 8;
    const __half* Vg0 = QKV + ((size_t)b * SEQ + rr) * QLD + 2 * DM + h * DKH + cc4 * 8;
    const uint32_t physrc = phys(rr, cc4);

    auto issue_stage = [&](int jb, int st) {
        const uint32_t sb = smb + ST0 + st * STSZ;
        const __half* kgb = Kg0 + (size_t)jb * 64 * QLD;
#pragma unroll
        for (int kc = 0; kc < 2; kc++)
            CP_ASYNC(sb + kc * CH64 + physrc, kgb + kc * 32);
        const __half* vgb = Vg0 + (size_t)jb * 64 * QLD;
#pragma unroll
        for (int kc = 0; kc < 2; kc++)
            CP_ASYNC(sb + VOFF + kc * CH64 + physrc, vgb + kc * 32);
        if (tid < 16)
            CP_ASYNC(sb + MOFF + tid * 16, mask + (size_t)b * SEQ + jb * 64 + tid * 4);
    };

#pragma unroll
    for (int kc = 0; kc < 2; kc++)
#pragma unroll
        for (int it = 0; it < 2; it++)
            CP_ASYNC(smb + QOFF + kc * CH128 + physrc + it * 32 * 128,
                     Qg + (size_t)it * 64 * QLD + kc * 32);
    issue_stage(0, 0);
    CP_COMMIT();
    issue_stage(1, 1);
    CP_COMMIT();
    CP_WAIT(1);
    __syncthreads();

    uint32_t qa[4][4];
    {
        const uint32_t qbase0 = phys(lane & 15, (lane >> 4)) + wid * 1024;
        const uint32_t qbase1 = phys(lane & 15, 2 + (lane >> 4)) + wid * 1024;
#pragma unroll
        for (int kc = 0; kc < 2; kc++) {
            LDSM_X4(qa[kc * 2][0], qa[kc * 2][1], qa[kc * 2][2], qa[kc * 2][3],
                    smb + QOFF + kc * CH128 + qbase0);
            LDSM_X4(qa[kc * 2 + 1][0], qa[kc * 2 + 1][1], qa[kc * 2 + 1][2], qa[kc * 2 + 1][3],
                    smb + QOFF + kc * CH128 + qbase1);
        }
    }

    const uint32_t bb0 = phys(((lane >> 4) << 3) + (lane & 7), ((lane >> 3) & 1));
    const uint32_t bb1 = phys(((lane >> 4) << 3) + (lane & 7), 2 + ((lane >> 3) & 1));
    const uint32_t vtb0 = phys(lane & 15, (lane >> 4));
    const uint32_t vtb1 = phys(lane & 15, 2 + (lane >> 4));

    float O[8][4];
#pragma unroll
    for (int i = 0; i < 8; i++)
#pragma unroll
        for (int j = 0; j < 4; j++) O[i][j] = 0.f;
    float l0 = 0.f, l1 = 0.f;

    for (int j = 0; j < NJ; j++) {
        const uint32_t sb = smb + ST0 + (j & 1) * STSZ;
        const int* msm = (const int*)(sm + ST0 + (j & 1) * STSZ + MOFF);

        float s[8][4];
#pragma unroll
        for (int i = 0; i < 8; i++)
#pragma unroll
            for (int k = 0; k < 4; k++) s[i][k] = 0.f;
#pragma unroll
        for (int kidx = 0; kidx < 4; kidx++) {
            const uint32_t cb = sb + (kidx >> 1) * CH64 + ((kidx & 1) ? bb1 : bb0);
#pragma unroll
            for (int np = 0; np < 4; np++) {
                uint32_t r0, r1, r2, r3;
                LDSM_X4(r0, r1, r2, r3, cb + np * 1024);
                uint32_t p0[2] = {r0, r1}, p1[2] = {r2, r3};
                MMA_F16(s[2 * np], qa[kidx], p0);
                MMA_F16(s[2 * np + 1], qa[kidx], p1);
            }
        }

        float sum0 = 0.f, sum1 = 0.f;
#pragma unroll
        for (int nt = 0; nt < 8; nt++) {
            const int c0 = nt * 8 + t4 * 2;
            const float a0 = msm[c0] ? 0.f : -1.0e9f;
            const float a1 = msm[c0 + 1] ? 0.f : -1.0e9f;
            s[nt][0] = exp2f(fmaf(s[nt][0], SCLL2E, a0));
            s[nt][1] = exp2f(fmaf(s[nt][1], SCLL2E, a1));
            s[nt][2] = exp2f(fmaf(s[nt][2], SCLL2E, a0));
            s[nt][3] = exp2f(fmaf(s[nt][3], SCLL2E, a1));
            sum0 += s[nt][0] + s[nt][1];
            sum1 += s[nt][2] + s[nt][3];
        }
        sum0 += __shfl_xor_sync(0xffffffffu, sum0, 1);
        sum0 += __shfl_xor_sync(0xffffffffu, sum0, 2);
        sum1 += __shfl_xor_sync(0xffffffffu, sum1, 1);
        sum1 += __shfl_xor_sync(0xffffffffu, sum1, 2);
        l0 += sum0;
        l1 += sum1;

#pragma unroll
        for (int kt = 0; kt < 4; kt++) {
            uint32_t pa[4];
            PACK_F16X2(pa[0], s[2 * kt][0], s[2 * kt][1]);
            PACK_F16X2(pa[1], s[2 * kt][2], s[2 * kt][3]);
            PACK_F16X2(pa[2], s[2 * kt + 1][0], s[2 * kt + 1][1]);
            PACK_F16X2(pa[3], s[2 * kt + 1][2], s[2 * kt + 1][3]);
#pragma unroll
            for (int np = 0; np < 4; np++) {
                uint32_t r0, r1, r2, r3;
                LDSM_X4_T(r0, r1, r2, r3,
                          sb + VOFF + (np >> 1) * CH64 + ((np & 1) ? vtb1 : vtb0) + kt * 1024);
                uint32_t p0[2] = {r0, r1}, p1[2] = {r2, r3};
                MMA_F16(O[2 * np], pa, p0);
                MMA_F16(O[2 * np + 1], pa, p1);
            }
        }

        __syncthreads();
        if (j + 2 < NJ) { issue_stage(j + 2, j & 1); CP_COMMIT(); CP_WAIT(1); }
        else if (j + 1 < NJ) { CP_WAIT(0); }
        __syncthreads();
    }

    const float inv0 = 1.f / l0, inv1 = 1.f / l1;
    const int q0 = qb * 128 + wid * 16 + gid;
    __half* C1 = CTX + ((size_t)(b * SEQ + q0)) * DM + h * DKH;
    __half* C2 = C1 + 8 * DM;
#pragma unroll
    for (int nt = 0; nt < 8; nt++) {
        const int cc = nt * 8 + t4 * 2;
        ushort2 o1, o2;
        o1.x = hfu(O[nt][0] * inv0); o1.y = hfu(O[nt][1] * inv0);
        o2.x = hfu(O[nt][2] * inv1); o2.y = hfu(O[nt][3] * inv1);
        *(ushort2*)(C1 + cc) = o1;
        *(ushort2*)(C2 + cc) = o2;
    }
}

// ======================= prologue kernels =======================
__global__ void f32_to_half_k(const float* __restrict__ in, __half* __restrict__ out, int n4)
{
    int i = blockIdx.x * 256 + threadIdx.x;
    if (i < n4) {
        float4 v = *(const float4*)(in + (size_t)i * 4);
        ushort4 o;
        o.x = hfu(v.x); o.y = hfu(v.y); o.z = hfu(v.z); o.w = hfu(v.w);
        *(ushort4*)(out + (size_t)i * 4) = o;
    }
}

__global__ void prep_w_k(const float* __restrict__ Wq, const float* __restrict__ Wk,
                         const float* __restrict__ Wv, const float* __restrict__ Wo,
                         const float* __restrict__ W1, const float* __restrict__ W2,
                         __half* __restrict__ WQKVT, __half* __restrict__ WOT,
                         __half* __restrict__ W1T, __half* __restrict__ W2T,
                         const float* __restrict__ bq, const float* __restrict__ bk,
                         const float* __restrict__ bv, float* __restrict__ BQKV, int base)
{
    __shared__ float t[32][33];
    const int idx = base + blockIdx.x;
    const int tx = threadIdx.x, ty = threadIdx.y;
    const int lt = ty * 32 + tx;

    if (idx == 0) {
        for (int i = lt; i < DM; i += 256) {
            BQKV[i] = bq[i];
            BQKV[i + DM] = bk[i];
            BQKV[i + 2 * DM] = bv[i];
        }
    }

    const float* in;
    __half* out;
    int K, N, n0, k0;
    if (idx < 4096) {
        const int w = idx >> 10, tile = idx & 1023;
        in = (w == 0) ? Wq : (w == 1) ? Wk : (w == 2) ? Wv : Wo;
        out = (w == 3) ? WOT : WQKVT + (size_t)w * DM * DM;
        K = DM; N = DM;
        n0 = (tile & 31) * 32; k0 = (tile >> 5) * 32;
    } else if (idx < 8192) {
        const int tile = idx - 4096;
        in = W1; out = W1T; K = DM; N = DFF;
        n0 = (tile & 127) * 32; k0 = (tile >> 7) * 32;
    } else {
        const int tile = idx - 8192;
        in = W2; out = W2T; K = DFF; N = DM;
        n0 = (tile & 31) * 32; k0 = (tile >> 5) * 32;
    }

    for (int j = ty; j < 32; j += 8) t[j][tx] = in[(size_t)(k0 + j) * N + n0 + tx];
    __syncthreads();
    for (int j = ty; j < 32; j += 8)
        out[(size_t)(n0 + j) * K + k0 + tx] = __float2half_rn(t[tx][j]);
}

// ======================= reductions / LN =======================
__device__ __forceinline__ float blkSum(float v, float* red)
{
#pragma unroll
    for (int o = 16; o > 0; o >>= 1) v += __shfl_xor_sync(0xffffffffu, v, o);
    int w = threadIdx.x >> 5, l = threadIdx.x & 31;
    if (l == 0) red[w] = v;
    __syncthreads();
    if (threadIdx.x < 8) {
        v = red[threadIdx.x];
#pragma unroll
        for (int o = 4; o > 0; o >>= 1) v += __shfl_xor_sync(0xffu, v, o);
        if (threadIdx.x == 0) red[0] = v;
    }
    __syncthreads();
    float r = red[0];
    __syncthreads();
    return r;
}

template<bool EMIT_H>
__global__ void addln_k(const float* __restrict__ a, const float* __restrict__ bres,
                        const float* __restrict__ g, const float* __restrict__ be,
                        float* __restrict__ out, __half* __restrict__ outh)
{
    __shared__ float red[32];
    const long long row = blockIdx.x;
    const float* pa = a + row * DM;
    const float* pb = bres + row * DM;
    const int tid = threadIdx.x;
    float v[4], s = 0.f, s2 = 0.f;
    {
        float4 xa = *(const float4*)(pa + tid * 4);
        float4 xb = *(const float4*)(pb + tid * 4);
        v[0] = xa.x + xb.x; v[1] = xa.y + xb.y;
        v[2] = xa.z + xb.z; v[3] = xa.w + xb.w;
#pragma unroll
        for (int j = 0; j < 4; j++) { s += v[j]; s2 += v[j] * v[j]; }
    }
    s = blkSum(s, red);
    s2 = blkSum(s2, red);
    float mu = s * (1.f / DM);
    float var = s2 * (1.f / DM) - mu * mu;
    float inv = rsqrtf(var + 1e-5f);
    float4 gv = *(const float4*)(g + tid * 4);
    float4 bv = *(const float4*)(be + tid * 4);
    float o0 = (v[0] - mu) * inv * gv.x + bv.x;
    float o1 = (v[1] - mu) * inv * gv.y + bv.y;
    float o2 = (v[2] - mu) * inv * gv.z + bv.z;
    float o3 = (v[3] - mu) * inv * gv.w + bv.w;
    *(float4*)(out + row * DM + tid * 4) = make_float4(o0, o1, o2, o3);
    if (EMIT_H) {
        ushort4 oh;
        oh.x = hfu(o0); oh.y = hfu(o1); oh.z = hfu(o2); oh.w = hfu(o3);
        *(ushort4*)(outh + row * DM + tid * 4) = oh;
    }
}

// ======================= launch =======================
extern "C" void kernel_launch(void* const* d_in, const int* in_sizes, int n_in,
                              void* d_out, int out_size)
{
    const float* x    = (const float*)d_in[0];
    const int*   mask = (const int*)  d_in[1];
    const float* Wq = (const float*)d_in[2];  const float* bq = (const float*)d_in[3];
    const float* Wk = (const float*)d_in[4];  const float* bk = (const float*)d_in[5];
    const float* Wv = (const float*)d_in[6];  const float* bv = (const float*)d_in[7];
    const float* Wo = (const float*)d_in[8];  const float* bo = (const float*)d_in[9];
    const float* W1 = (const float*)d_in[10]; const float* b1 = (const float*)d_in[11];
    const float* W2 = (const float*)d_in[12]; const float* b2 = (const float*)d_in[13];
    const float* g1 = (const float*)d_in[14]; const float* be1 = (const float*)d_in[15];
    const float* g2 = (const float*)d_in[16]; const float* be2 = (const float*)d_in[17];
    float* out = (float*)d_out;

    float *TMP, *H, *BQKV;
    __half *XH, *QKV, *CTX, *WQKVT, *WOT, *W1T, *W2T, *HH, *FF;
    cudaGetSymbolAddress((void**)&TMP, g_tmp);
    cudaGetSymbolAddress((void**)&H, g_h);
    cudaGetSymbolAddress((void**)&XH, g_xh);
    cudaGetSymbolAddress((void**)&QKV, g_qkv);
    cudaGetSymbolAddress((void**)&CTX, g_ctx);
    cudaGetSymbolAddress((void**)&WQKVT, g_WqkvT);
    cudaGetSymbolAddress((void**)&WOT, g_WoT);
    cudaGetSymbolAddress((void**)&W1T, g_W1T);
    cudaGetSymbolAddress((void**)&W2T, g_W2T);
    cudaGetSymbolAddress((void**)&HH, g_hh);
    cudaGetSymbolAddress((void**)&FF, g_ff);
    cudaGetSymbolAddress((void**)&BQKV, g_bqkv);

    const int SMGM = 3 * 32 * 1024;           // 98304
    const int SMFL = 16384 + 2 * 16640;       // 49664
    cudaFuncSetAttribute(mma_gemm<0, 0>, cudaFuncAttributeMaxDynamicSharedMemorySize, SMGM);
    cudaFuncSetAttribute(mma_gemm<0, 1>, cudaFuncAttributeMaxDynamicSharedMemorySize, SMGM);
    cudaFuncSetAttribute(mma_gemm<1, 1>, cudaFuncAttributeMaxDynamicSharedMemorySize, SMGM);
    cudaFuncSetAttribute(mma_gemm<2, 0>, cudaFuncAttributeMaxDynamicSharedMemorySize, SMGM);
    cudaFuncSetAttribute(flash_k, cudaFuncAttributeMaxDynamicSharedMemorySize, SMFL);

    const dim3 t32(32, 8);

    // launch 1: x -> half
    f32_to_half_k<<<(NT * DM / 4 + 255) / 256, 256>>>(x, XH, NT * DM / 4);
    // launch 2: Wq/Wk/Wv transposes + bias concat
    prep_w_k<<<3072, t32>>>(Wq, Wk, Wv, Wo, W1, W2, WQKVT, WOT, W1T, W2T, bq, bk, bv, BQKV, 0);
    // launch 3: Wo/W1/W2 transposes
    prep_w_k<<<9216, t32>>>(Wq, Wk, Wv, Wo, W1, W2, WQKVT, WOT, W1T, W2T, bq, bk, bv, BQKV, 3072);
    // launch 4: fused QKV projection (f16 accumulate — diluted branch)
    {
        dim3 g(3 * DM / 128, NT / 128, 1);
        mma_gemm<1, 1><<<g, 256, SMGM>>>(XH, WQKVT, BQKV, (char*)QKV, DM, DM, DM, 3 * DM, 1.f);
    }
    // launch 5: flash attention
    flash_k<<<dim3(SEQ / 128, 64), 256, SMFL>>>(QKV, mask, CTX);
    // launch 6: attn_out = ctx @ Wo + bo (f16 accumulate — diluted branch)
    {
        dim3 g(DM / 128, NT / 128, 1);
        mma_gemm<0, 1><<<g, 256, SMGM>>>(CTX, WOT, bo, (char*)TMP, DM, DM, DM, DM, 1.f);
    }
    // launch 7: LN1
    addln_k<true><<<NT, 256>>>(x, TMP, g1, be1, H, HH);
    // launch 8: FFN1 (f32 accumulate — precision-critical)
    {
        dim3 g(DFF / 128, NT / 128, 1);
        mma_gemm<2, 0><<<g, 256, SMGM>>>(HH, W1T, b1, (char*)FF, DM, DM, DM, DFF, 1.f);
    }
    // launch 9: FFN2 (f32 accumulate)
    {
        dim3 g(DM / 128, NT / 128, 1);
        mma_gemm<0, 0><<<g, 256, SMGM>>>(FF, W2T, b2, (char*)TMP, DFF, DFF, DFF, DM, 1.f);
    }
    // launch 10: LN2
    addln_k<false><<<NT, 256>>>(H, TMP, g2, be2, out, nullptr);
}

// round 15
// speedup vs baseline: 1.0227x; 1.0226x over previous
#include <cuda_runtime.h>
#include <cuda_fp16.h>
#include <cstdint>

#define BATCH 4
#define SEQ   1024
#define NT    4096
#define DM    1024
#define NH    16
#define DKH   64
#define DFF   4096

// ======================= device scratch =======================
__device__ __align__(16) float g_tmp[(size_t)NT * DM];
__device__ __align__(16) float g_h[(size_t)NT * DM];
__device__ __align__(16) __half g_xh [(size_t)NT * DM];
__device__ __align__(16) __half g_qkv[(size_t)NT * 3 * DM];
__device__ __align__(16) __half g_ctx[(size_t)NT * DM];
__device__ __align__(16) __half g_WqkvT[(size_t)3 * DM * DM];
__device__ __align__(16) __half g_WoT[(size_t)DM * DM];
__device__ __align__(16) __half g_W1T[(size_t)DFF * DM];
__device__ __align__(16) __half g_W2T[(size_t)DM * DFF];
__device__ __align__(16) __half g_hh [(size_t)NT * DM];
__device__ __align__(16) __half g_ff [(size_t)NT * DFF];
__device__ __align__(16) float  g_bqkv[3 * DM];

// ======================= asm helpers (compute_80-level only) =======================
__device__ __forceinline__ uint32_t smem_u32(const void* p) {
    uint32_t a;
    asm("{ .reg .u64 t; cvta.to.shared.u64 t, %1; cvt.u32.u64 %0, t; }" : "=r"(a) : "l"(p));
    return a;
}
#define CP_ASYNC(s, g) \
    asm volatile("cp.async.cg.shared.global [%0], [%1], 16;" :: "r"(s), "l"(g) : "memory")
#define CP_COMMIT() asm volatile("cp.async.commit_group;" ::: "memory")
#define CP_WAIT(n)  asm volatile("cp.async.wait_group %0;" :: "n"(n) : "memory")

#define LDSM_X4(r0, r1, r2, r3, a) \
    asm volatile("ldmatrix.sync.aligned.m8n8.x4.shared.b16 {%0,%1,%2,%3}, [%4];" \
        : "=r"(r0), "=r"(r1), "=r"(r2), "=r"(r3) : "r"(a))

#define LDSM_X4_T(r0, r1, r2, r3, a) \
    asm volatile("ldmatrix.sync.aligned.m8n8.x4.trans.shared.b16 {%0,%1,%2,%3}, [%4];" \
        : "=r"(r0), "=r"(r1), "=r"(r2), "=r"(r3) : "r"(a))

#define MMA_F16(d, a, b) \
    asm volatile("mma.sync.aligned.m16n8k16.row.col.f32.f16.f16.f32 " \
        "{%0,%1,%2,%3}, {%4,%5,%6,%7}, {%8,%9}, {%0,%1,%2,%3};" \
        : "+f"((d)[0]), "+f"((d)[1]), "+f"((d)[2]), "+f"((d)[3]) \
        : "r"((a)[0]), "r"((a)[1]), "r"((a)[2]), "r"((a)[3]), "r"((b)[0]), "r"((b)[1]))

#define PACK_F16X2(r, flo, fhi) \
    asm("cvt.rn.f16x2.f32 %0, %1, %2;" : "=r"(r) : "f"(fhi), "f"(flo))

// 64B-row swizzle (flash): phys(r+16,c)==phys(r,c)+1024.
__device__ __forceinline__ uint32_t phys(uint32_t r, uint32_t c) {
    return (r >> 1) * 128 + ((((r & 1) << 2) | c) ^ ((r >> 1) & 7)) * 16;
}
// 128B-row swizzle (GEMM).
__device__ __forceinline__ uint32_t phys128(uint32_t r, uint32_t c) {
    return r * 128 + ((c ^ (r & 7)) * 16);
}
__device__ __forceinline__ unsigned short hfu(float v) {
    return __half_as_ushort(__float2half_rn(v));
}

// ======================= mma.sync batched GEMM: BM=128, BN=128, BK=64, DEPTH=3 (R12 form) =======================
// C[M,N] = alpha*(A @ B^T) + bias. A:[M,K] half, B:[N,K] half row-major. K%64==0.
// OUT: 0=f32, 1=half, 2=relu half.
template<int OUT>
__global__ __launch_bounds__(256, 2)
void mma_gemm(const __half* __restrict__ A, const __half* __restrict__ B,
              const float* __restrict__ bias, char* __restrict__ Cptr,
              int K, int lda, int ldb, int ldc, float alpha)
{
    constexpr int DEPTH  = 3;
    constexpr int ABYTES = 128 * 128;       // 16 KB
    constexpr int STAGE  = 2 * ABYTES;      // 32 KB
    constexpr int NTL    = 8;               // warp: 32 rows x 64 cols

    extern __shared__ char sm[];
    const uint32_t smb = smem_u32(sm);

    const int tid = threadIdx.x;
    const int wid = tid >> 5, lane = tid & 31;
    const int wRow = (wid & 3) * 32;
    const int wCol = (wid >> 2) * 64;
    const int row0 = blockIdx.y * 128;
    const int col0 = blockIdx.x * 128;

    const __half* Ag[4]; const __half* Bg[4]; uint32_t Asm[4], Bsm[4];
#pragma unroll
    for (int i = 0; i < 4; i++) {
        int idx = tid + i * 256;
        int r = idx >> 3, c = idx & 7;
        Ag[i]  = A + (size_t)(row0 + r) * lda + c * 8;
        Bg[i]  = B + (size_t)(col0 + r) * ldb + c * 8;
        Asm[i] = phys128(r, c);
        Bsm[i] = ABYTES + phys128(r, c);
    }

    const uint32_t ra0 = (uint32_t)(wRow + (lane & 15)) * 128;
    const uint32_t rmA = (uint32_t)(lane & 15) & 7;
    const uint32_t sA  = lane >> 4;
    const uint32_t rb0 = (uint32_t)(wCol + ((lane >> 4) << 3) + (lane & 7)) * 128;
    const uint32_t rmB = (uint32_t)lane & 7;
    const uint32_t sB  = (lane >> 3) & 1;

    float acc[2][NTL][4];
#pragma unroll
    for (int i = 0; i < 2; i++)
#pragma unroll
        for (int j = 0; j < NTL; j++)
#pragma unroll
            for (int k = 0; k < 4; k++) acc[i][j][k] = 0.f;

    const int NC = K / 64;
    const int PRE = NC < (DEPTH - 1) ? NC : (DEPTH - 1);
    for (int s = 0; s < PRE; s++) {
#pragma unroll
        for (int i = 0; i < 4; i++) {
            CP_ASYNC(smb + s * STAGE + Asm[i], Ag[i] + s * 64);
            CP_ASYNC(smb + s * STAGE + Bsm[i], Bg[i] + s * 64);
        }
        CP_COMMIT();
    }
    int idx = PRE;
    int stC = 0, stL = PRE % DEPTH;
    for (int cch = 0; cch < NC; cch++) {
        const int rem = NC - 1 - cch;
        if (rem >= 1) { CP_WAIT(1); } else { CP_WAIT(0); }
        __syncthreads();
        if (idx < NC) {
#pragma unroll
            for (int i = 0; i < 4; i++) {
                CP_ASYNC(smb + stL * STAGE + Asm[i], Ag[i] + idx * 64);
                CP_ASYNC(smb + stL * STAGE + Bsm[i], Bg[i] + idx * 64);
            }
            CP_COMMIT();
            idx++;
            stL = (stL + 1 == DEPTH) ? 0 : stL + 1;
        }
        const uint32_t sb = smb + stC * STAGE;
        stC = (stC + 1 == DEPTH) ? 0 : stC + 1;
#pragma unroll
        for (int kk = 0; kk < 4; kk++) {
            const uint32_t cA = ((2 * kk + sA) ^ rmA) * 16;
            const uint32_t cB = ((2 * kk + sB) ^ rmB) * 16;
            uint32_t a[2][4], b[NTL][2];
#pragma unroll
            for (int mt = 0; mt < 2; mt++)
                LDSM_X4(a[mt][0], a[mt][1], a[mt][2], a[mt][3],
                        sb + ra0 + mt * 2048 + cA);
#pragma unroll
            for (int np = 0; np < 4; np++)
                LDSM_X4(b[2 * np][0], b[2 * np][1], b[2 * np + 1][0], b[2 * np + 1][1],
                        sb + ABYTES + rb0 + np * 2048 + cB);
#pragma unroll
            for (int mt = 0; mt < 2; mt++)
#pragma unroll
                for (int nt = 0; nt < NTL; nt++)
                    MMA_F16(acc[mt][nt], a[mt], b[nt]);
        }
    }

    const int gid = lane >> 2, t4 = lane & 3;
#pragma unroll
    for (int mt = 0; mt < 2; mt++) {
        const int r1 = row0 + wRow + mt * 16 + gid;
        const long long ro1 = (long long)r1 * ldc;
        const long long ro2 = ro1 + 8LL * ldc;
#pragma unroll
        for (int nt = 0; nt < NTL; nt++) {
            const int cc = col0 + wCol + nt * 8 + t4 * 2;
            const float b0 = bias ? bias[cc] : 0.f;
            const float b1 = bias ? bias[cc + 1] : 0.f;
            float v0 = acc[mt][nt][0] * alpha + b0;
            float v1 = acc[mt][nt][1] * alpha + b1;
            float v2 = acc[mt][nt][2] * alpha + b0;
            float v3 = acc[mt][nt][3] * alpha + b1;
            if constexpr (OUT == 0) {
                float* C = (float*)Cptr;
                *(float2*)(C + ro1 + cc) = make_float2(v0, v1);
                *(float2*)(C + ro2 + cc) = make_float2(v2, v3);
            } else {
                if constexpr (OUT == 2) {
                    v0 = fmaxf(v0, 0.f); v1 = fmaxf(v1, 0.f);
                    v2 = fmaxf(v2, 0.f); v3 = fmaxf(v3, 0.f);
                }
                __half* C = (__half*)Cptr;
                ushort2 o1, o2;
                o1.x = hfu(v0); o1.y = hfu(v1);
                o2.x = hfu(v2); o2.y = hfu(v3);
                *(ushort2*)(C + ro1 + cc) = o1;
                *(ushort2*)(C + ro2 + cc) = o2;
            }
        }
    }
}

// ======================= flash attention: no-max-tracking softmax =======================
__global__ __launch_bounds__(256, 2)
void flash_k(const __half* __restrict__ QKV, const int* __restrict__ mask,
             __half* __restrict__ CTX)
{
    constexpr int QLD   = 3 * DM;
    constexpr int CH128 = 8192;
    constexpr int CH64  = 4096;
    constexpr int QOFF  = 0;
    constexpr int ST0   = 16384;
    constexpr int VOFF  = 8192;
    constexpr int MOFF  = 16384;
    constexpr int STSZ  = 16640;
    constexpr int NJ    = SEQ / 64;
    constexpr float SCLL2E = 0.125f * 1.44269504f;

    extern __shared__ char sm[];
    const uint32_t smb = smem_u32(sm);

    const int tid = threadIdx.x;
    const int wid = tid >> 5, lane = tid & 31;
    const int gid = lane >> 2, t4 = lane & 3;
    const int qb = blockIdx.x, z = blockIdx.y;
    const int b = z >> 4, h = z & 15;

    const int rr = tid >> 2, cc4 = tid & 3;
    const size_t qrow0 = (size_t)(b * SEQ + qb * 128);
    const __half* Qg  = QKV + (qrow0 + rr) * QLD + h * DKH + cc4 * 8;
    const __half* Kg0 = QKV + ((size_t)b * SEQ + rr) * QLD + DM + h * DKH + cc4 * 8;
    const __half* Vg0 = QKV + ((size_t)b * SEQ + rr) * QLD + 2 * DM + h * DKH + cc4 * 8;
    const uint32_t physrc = phys(rr, cc4);

    auto issue_stage = [&](int jb, int st) {
        const uint32_t sb = smb + ST0 + st * STSZ;
        const __half* kgb = Kg0 + (size_t)jb * 64 * QLD;
#pragma unroll
        for (int kc = 0; kc < 2; kc++)
            CP_ASYNC(sb + kc * CH64 + physrc, kgb + kc * 32);
        const __half* vgb = Vg0 + (size_t)jb * 64 * QLD;
#pragma unroll
        for (int kc = 0; kc < 2; kc++)
            CP_ASYNC(sb + VOFF + kc * CH64 + physrc, vgb + kc * 32);
        if (tid < 16)
            CP_ASYNC(sb + MOFF + tid * 16, mask + (size_t)b * SEQ + jb * 64 + tid * 4);
    };

#pragma unroll
    for (int kc = 0; kc < 2; kc++)
#pragma unroll
        for (int it = 0; it < 2; it++)
            CP_ASYNC(smb + QOFF + kc * CH128 + physrc + it * 32 * 128,
                     Qg + (size_t)it * 64 * QLD + kc * 32);
    issue_stage(0, 0);
    CP_COMMIT();
    issue_stage(1, 1);
    CP_COMMIT();
    CP_WAIT(1);
    __syncthreads();

    uint32_t qa[4][4];
    {
        const uint32_t qbase0 = phys(lane & 15, (lane >> 4)) + wid * 1024;
        const uint32_t qbase1 = phys(lane & 15, 2 + (lane >> 4)) + wid * 1024;
#pragma unroll
        for (int kc = 0; kc < 2; kc++) {
            LDSM_X4(qa[kc * 2][0], qa[kc * 2][1], qa[kc * 2][2], qa[kc * 2][3],
                    smb + QOFF + kc * CH128 + qbase0);
            LDSM_X4(qa[kc * 2 + 1][0], qa[kc * 2 + 1][1], qa[kc * 2 + 1][2], qa[kc * 2 + 1][3],
                    smb + QOFF + kc * CH128 + qbase1);
        }
    }

    const uint32_t bb0 = phys(((lane >> 4) << 3) + (lane & 7), ((lane >> 3) & 1));
    const uint32_t bb1 = phys(((lane >> 4) << 3) + (lane & 7), 2 + ((lane >> 3) & 1));
    const uint32_t vtb0 = phys(lane & 15, (lane >> 4));
    const uint32_t vtb1 = phys(lane & 15, 2 + (lane >> 4));

    float O[8][4];
#pragma unroll
    for (int i = 0; i < 8; i++)
#pragma unroll
        for (int j = 0; j < 4; j++) O[i][j] = 0.f;
    float l0 = 0.f, l1 = 0.f;

    for (int j = 0; j < NJ; j++) {
        const uint32_t sb = smb + ST0 + (j & 1) * STSZ;
        const int* msm = (const int*)(sm + ST0 + (j & 1) * STSZ + MOFF);

        float s[8][4];
#pragma unroll
        for (int i = 0; i < 8; i++)
#pragma unroll
            for (int k = 0; k < 4; k++) s[i][k] = 0.f;
#pragma unroll
        for (int kidx = 0; kidx < 4; kidx++) {
            const uint32_t cb = sb + (kidx >> 1) * CH64 + ((kidx & 1) ? bb1 : bb0);
#pragma unroll
            for (int np = 0; np < 4; np++) {
                uint32_t r0, r1, r2, r3;
                LDSM_X4(r0, r1, r2, r3, cb + np * 1024);
                uint32_t p0[2] = {r0, r1}, p1[2] = {r2, r3};
                MMA_F16(s[2 * np], qa[kidx], p0);
                MMA_F16(s[2 * np + 1], qa[kidx], p1);
            }
        }

        float sum0 = 0.f, sum1 = 0.f;
#pragma unroll
        for (int nt = 0; nt < 8; nt++) {
            const int c0 = nt * 8 + t4 * 2;
            const float a0 = msm[c0] ? 0.f : -1.0e9f;
            const float a1 = msm[c0 + 1] ? 0.f : -1.0e9f;
            s[nt][0] = exp2f(fmaf(s[nt][0], SCLL2E, a0));
            s[nt][1] = exp2f(fmaf(s[nt][1], SCLL2E, a1));
            s[nt][2] = exp2f(fmaf(s[nt][2], SCLL2E, a0));
            s[nt][3] = exp2f(fmaf(s[nt][3], SCLL2E, a1));
            sum0 += s[nt][0] + s[nt][1];
            sum1 += s[nt][2] + s[nt][3];
        }
        sum0 += __shfl_xor_sync(0xffffffffu, sum0, 1);
        sum0 += __shfl_xor_sync(0xffffffffu, sum0, 2);
        sum1 += __shfl_xor_sync(0xffffffffu, sum1, 1);
        sum1 += __shfl_xor_sync(0xffffffffu, sum1, 2);
        l0 += sum0;
        l1 += sum1;

#pragma unroll
        for (int kt = 0; kt < 4; kt++) {
            uint32_t pa[4];
            PACK_F16X2(pa[0], s[2 * kt][0], s[2 * kt][1]);
            PACK_F16X2(pa[1], s[2 * kt][2], s[2 * kt][3]);
            PACK_F16X2(pa[2], s[2 * kt + 1][0], s[2 * kt + 1][1]);
            PACK_F16X2(pa[3], s[2 * kt + 1][2], s[2 * kt + 1][3]);
#pragma unroll
            for (int np = 0; np < 4; np++) {
                uint32_t r0, r1, r2, r3;
                LDSM_X4_T(r0, r1, r2, r3,
                          sb + VOFF + (np >> 1) * CH64 + ((np & 1) ? vtb1 : vtb0) + kt * 1024);
                uint32_t p0[2] = {r0, r1}, p1[2] = {r2, r3};
                MMA_F16(O[2 * np], pa, p0);
                MMA_F16(O[2 * np + 1], pa, p1);
            }
        }

        __syncthreads();
        if (j + 2 < NJ) { issue_stage(j + 2, j & 1); CP_COMMIT(); CP_WAIT(1); }
        else if (j + 1 < NJ) { CP_WAIT(0); }
        __syncthreads();
    }

    const float inv0 = 1.f / l0, inv1 = 1.f / l1;
    const int q0 = qb * 128 + wid * 16 + gid;
    __half* C1 = CTX + ((size_t)(b * SEQ + q0)) * DM + h * DKH;
    __half* C2 = C1 + 8 * DM;
#pragma unroll
    for (int nt = 0; nt < 8; nt++) {
        const int cc = nt * 8 + t4 * 2;
        ushort2 o1, o2;
        o1.x = hfu(O[nt][0] * inv0); o1.y = hfu(O[nt][1] * inv0);
        o2.x = hfu(O[nt][2] * inv1); o2.y = hfu(O[nt][3] * inv1);
        *(ushort2*)(C1 + cc) = o1;
        *(ushort2*)(C2 + cc) = o2;
    }
}

// ======================= unified prologue: all weight transposes + bias concat + x->half =======================
// blocks [0,4096): Wq/Wk/Wv/Wo tiles; [4096,8192): W1; [8192,12288): W2;
// blocks [12288,16384): x -> half, 1024 floats per block.
__global__ void prep_all_k(const float* __restrict__ Wq, const float* __restrict__ Wk,
                           const float* __restrict__ Wv, const float* __restrict__ Wo,
                           const float* __restrict__ W1, const float* __restrict__ W2,
                           __half* __restrict__ WQKVT, __half* __restrict__ WOT,
                           __half* __restrict__ W1T, __half* __restrict__ W2T,
                           const float* __restrict__ bq, const float* __restrict__ bk,
                           const float* __restrict__ bv, float* __restrict__ BQKV,
                           const float* __restrict__ x, __half* __restrict__ XH)
{
    __shared__ float t[32][33];
    const int idx = blockIdx.x;
    const int tx = threadIdx.x, ty = threadIdx.y;
    const int lt = ty * 32 + tx;

    if (idx >= 12288) {
        // x -> half, 1024 f32 per block (256 threads x float4)
        const size_t off = ((size_t)(idx - 12288) * 1024) + (size_t)lt * 4;
        float4 v = *(const float4*)(x + off);
        ushort4 o;
        o.x = hfu(v.x); o.y = hfu(v.y); o.z = hfu(v.z); o.w = hfu(v.w);
        *(ushort4*)(XH + off) = o;
        return;
    }

    if (idx == 0) {
        for (int i = lt; i < DM; i += 256) {
            BQKV[i] = bq[i];
            BQKV[i + DM] = bk[i];
            BQKV[i + 2 * DM] = bv[i];
        }
    }

    const float* in;
    __half* out;
    int K, N, n0, k0;
    if (idx < 4096) {
        const int w = idx >> 10, tile = idx & 1023;
        in = (w == 0) ? Wq : (w == 1) ? Wk : (w == 2) ? Wv : Wo;
        out = (w == 3) ? WOT : WQKVT + (size_t)w * DM * DM;
        K = DM; N = DM;
        n0 = (tile & 31) * 32; k0 = (tile >> 5) * 32;
    } else if (idx < 8192) {
        const int tile = idx - 4096;
        in = W1; out = W1T; K = DM; N = DFF;
        n0 = (tile & 127) * 32; k0 = (tile >> 7) * 32;
    } else {
        const int tile = idx - 8192;
        in = W2; out = W2T; K = DFF; N = DM;
        n0 = (tile & 31) * 32; k0 = (tile >> 5) * 32;
    }

    for (int j = ty; j < 32; j += 8) t[j][tx] = in[(size_t)(k0 + j) * N + n0 + tx];
    __syncthreads();
    for (int j = ty; j < 32; j += 8)
        out[(size_t)(n0 + j) * K + k0 + tx] = __float2half_rn(t[tx][j]);
}

// ======================= reductions / LN =======================
__device__ __forceinline__ float blkSum(float v, float* red)
{
#pragma unroll
    for (int o = 16; o > 0; o >>= 1) v += __shfl_xor_sync(0xffffffffu, v, o);
    int w = threadIdx.x >> 5, l = threadIdx.x & 31;
    if (l == 0) red[w] = v;
    __syncthreads();
    if (threadIdx.x < 8) {
        v = red[threadIdx.x];
#pragma unroll
        for (int o = 4; o > 0; o >>= 1) v += __shfl_xor_sync(0xffu, v, o);
        if (threadIdx.x == 0) red[0] = v;
    }
    __syncthreads();
    float r = red[0];
    __syncthreads();
    return r;
}

template<bool EMIT_H>
__global__ void addln_k(const float* __restrict__ a, const float* __restrict__ bres,
                        const float* __restrict__ g, const float* __restrict__ be,
                        float* __restrict__ out, __half* __restrict__ outh)
{
    __shared__ float red[32];
    const long long row = blockIdx.x;
    const float* pa = a + row * DM;
    const float* pb = bres + row * DM;
    const int tid = threadIdx.x;
    float v[4], s = 0.f, s2 = 0.f;
    {
        float4 xa = *(const float4*)(pa + tid * 4);
        float4 xb = *(const float4*)(pb + tid * 4);
        v[0] = xa.x + xb.x; v[1] = xa.y + xb.y;
        v[2] = xa.z + xb.z; v[3] = xa.w + xb.w;
#pragma unroll
        for (int j = 0; j < 4; j++) { s += v[j]; s2 += v[j] * v[j]; }
    }
    s = blkSum(s, red);
    s2 = blkSum(s2, red);
    float mu = s * (1.f / DM);
    float var = s2 * (1.f / DM) - mu * mu;
    float inv = rsqrtf(var + 1e-5f);
    float4 gv = *(const float4*)(g + tid * 4);
    float4 bv = *(const float4*)(be + tid * 4);
    float o0 = (v[0] - mu) * inv * gv.x + bv.x;
    float o1 = (v[1] - mu) * inv * gv.y + bv.y;
    float o2 = (v[2] - mu) * inv * gv.z + bv.z;
    float o3 = (v[3] - mu) * inv * gv.w + bv.w;
    *(float4*)(out + row * DM + tid * 4) = make_float4(o0, o1, o2, o3);
    if (EMIT_H) {
        ushort4 oh;
        oh.x = hfu(o0); oh.y = hfu(o1); oh.z = hfu(o2); oh.w = hfu(o3);
        *(ushort4*)(outh + row * DM + tid * 4) = oh;
    }
}

// ======================= launch =======================
extern "C" void kernel_launch(void* const* d_in, const int* in_sizes, int n_in,
                              void* d_out, int out_size)
{
    const float* x    = (const float*)d_in[0];
    const int*   mask = (const int*)  d_in[1];
    const float* Wq = (const float*)d_in[2];  const float* bq = (const float*)d_in[3];
    const float* Wk = (const float*)d_in[4];  const float* bk = (const float*)d_in[5];
    const float* Wv = (const float*)d_in[6];  const float* bv = (const float*)d_in[7];
    const float* Wo = (const float*)d_in[8];  const float* bo = (const float*)d_in[9];
    const float* W1 = (const float*)d_in[10]; const float* b1 = (const float*)d_in[11];
    const float* W2 = (const float*)d_in[12]; const float* b2 = (const float*)d_in[13];
    const float* g1 = (const float*)d_in[14]; const float* be1 = (const float*)d_in[15];
    const float* g2 = (const float*)d_in[16]; const float* be2 = (const float*)d_in[17];
    float* out = (float*)d_out;

    float *TMP, *H, *BQKV;
    __half *XH, *QKV, *CTX, *WQKVT, *WOT, *W1T, *W2T, *HH, *FF;
    cudaGetSymbolAddress((void**)&TMP, g_tmp);
    cudaGetSymbolAddress((void**)&H, g_h);
    cudaGetSymbolAddress((void**)&XH, g_xh);
    cudaGetSymbolAddress((void**)&QKV, g_qkv);
    cudaGetSymbolAddress((void**)&CTX, g_ctx);
    cudaGetSymbolAddress((void**)&WQKVT, g_WqkvT);
    cudaGetSymbolAddress((void**)&WOT, g_WoT);
    cudaGetSymbolAddress((void**)&W1T, g_W1T);
    cudaGetSymbolAddress((void**)&W2T, g_W2T);
    cudaGetSymbolAddress((void**)&HH, g_hh);
    cudaGetSymbolAddress((void**)&FF, g_ff);
    cudaGetSymbolAddress((void**)&BQKV, g_bqkv);

    const int SMGM = 3 * 32 * 1024;           // 98304
    const int SMFL = 16384 + 2 * 16640;       // 49664
    cudaFuncSetAttribute(mma_gemm<0>, cudaFuncAttributeMaxDynamicSharedMemorySize, SMGM);
    cudaFuncSetAttribute(mma_gemm<1>, cudaFuncAttributeMaxDynamicSharedMemorySize, SMGM);
    cudaFuncSetAttribute(mma_gemm<2>, cudaFuncAttributeMaxDynamicSharedMemorySize, SMGM);
    cudaFuncSetAttribute(flash_k, cudaFuncAttributeMaxDynamicSharedMemorySize, SMFL);

    const dim3 t32(32, 8);

    // launch 1: unified prologue (weights + biases + x->half)
    prep_all_k<<<16384, t32>>>(Wq, Wk, Wv, Wo, W1, W2, WQKVT, WOT, W1T, W2T,
                               bq, bk, bv, BQKV, x, XH);
    // launch 2: fused QKV projection
    {
        dim3 g(3 * DM / 128, NT / 128, 1);
        mma_gemm<1><<<g, 256, SMGM>>>(XH, WQKVT, BQKV, (char*)QKV, DM, DM, DM, 3 * DM, 1.f);
    }
    // launch 3: flash attention
    flash_k<<<dim3(SEQ / 128, 64), 256, SMFL>>>(QKV, mask, CTX);
    // launch 4: attn_out = ctx @ Wo + bo
    {
        dim3 g(DM / 128, NT / 128, 1);
        mma_gemm<0><<<g, 256, SMGM>>>(CTX, WOT, bo, (char*)TMP, DM, DM, DM, DM, 1.f);
    }
    // launch 5: LN1
    addln_k<true><<<NT, 256>>>(x, TMP, g1, be1, H, HH);
    // launch 6: FFN1
    {
        dim3 g(DFF / 128, NT / 128, 1);
        mma_gemm<2><<<g, 256, SMGM>>>(HH, W1T, b1, (char*)FF, DM, DM, DM, DFF, 1.f);
    }
    // launch 7: FFN2
    {
        dim3 g(DM / 128, NT / 128, 1);
        mma_gemm<0><<<g, 256, SMGM>>>(FF, W2T, b2, (char*)TMP, DFF, DFF, DFF, DM, 1.f);
    }
    // launch 8: LN2
    addln_k<false><<<NT, 256>>>(H, TMP, g2, be2, out, nullptr);
}

// round 16
// speedup vs baseline: 1.0326x; 1.0097x over previous
#include <cuda_runtime.h>
#include <cuda_fp16.h>
#include <cstdint>

#define BATCH 4
#define SEQ   1024
#define NT    4096
#define DM    1024
#define NH    16
#define DKH   64
#define DFF   4096

// ======================= device scratch =======================
__device__ __align__(16) float g_tmp[(size_t)NT * DM];
__device__ __align__(16) float g_h[(size_t)NT * DM];
__device__ __align__(16) __half g_xh [(size_t)NT * DM];
__device__ __align__(16) __half g_qkv[(size_t)NT * 3 * DM];
__device__ __align__(16) __half g_ctx[(size_t)NT * DM];
__device__ __align__(16) __half g_WqkvT[(size_t)3 * DM * DM];
__device__ __align__(16) __half g_WoT[(size_t)DM * DM];
__device__ __align__(16) __half g_W1T[(size_t)DFF * DM];
__device__ __align__(16) __half g_W2T[(size_t)DM * DFF];
__device__ __align__(16) __half g_hh [(size_t)NT * DM];
__device__ __align__(16) __half g_ff [(size_t)NT * DFF];
__device__ __align__(16) float  g_bqkv[3 * DM];

// ======================= asm helpers (compute_80-level only) =======================
__device__ __forceinline__ uint32_t smem_u32(const void* p) {
    uint32_t a;
    asm("{ .reg .u64 t; cvta.to.shared.u64 t, %1; cvt.u32.u64 %0, t; }" : "=r"(a) : "l"(p));
    return a;
}
#define CP_ASYNC(s, g) \
    asm volatile("cp.async.cg.shared.global [%0], [%1], 16;" :: "r"(s), "l"(g) : "memory")
#define CP_COMMIT() asm volatile("cp.async.commit_group;" ::: "memory")
#define CP_WAIT(n)  asm volatile("cp.async.wait_group %0;" :: "n"(n) : "memory")

#define LDSM_X4(r0, r1, r2, r3, a) \
    asm volatile("ldmatrix.sync.aligned.m8n8.x4.shared.b16 {%0,%1,%2,%3}, [%4];" \
        : "=r"(r0), "=r"(r1), "=r"(r2), "=r"(r3) : "r"(a))

#define LDSM_X4_T(r0, r1, r2, r3, a) \
    asm volatile("ldmatrix.sync.aligned.m8n8.x4.trans.shared.b16 {%0,%1,%2,%3}, [%4];" \
        : "=r"(r0), "=r"(r1), "=r"(r2), "=r"(r3) : "r"(a))

#define MMA_F16(d, a, b) \
    asm volatile("mma.sync.aligned.m16n8k16.row.col.f32.f16.f16.f32 " \
        "{%0,%1,%2,%3}, {%4,%5,%6,%7}, {%8,%9}, {%0,%1,%2,%3};" \
        : "+f"((d)[0]), "+f"((d)[1]), "+f"((d)[2]), "+f"((d)[3]) \
        : "r"((a)[0]), "r"((a)[1]), "r"((a)[2]), "r"((a)[3]), "r"((b)[0]), "r"((b)[1]))

#define PACK_F16X2(r, flo, fhi) \
    asm("cvt.rn.f16x2.f32 %0, %1, %2;" : "=r"(r) : "f"(fhi), "f"(flo))

// 64B-row swizzle (flash): phys(r+16,c)==phys(r,c)+1024.
__device__ __forceinline__ uint32_t phys(uint32_t r, uint32_t c) {
    return (r >> 1) * 128 + ((((r & 1) << 2) | c) ^ ((r >> 1) & 7)) * 16;
}
// 128B-row swizzle (GEMM).
__device__ __forceinline__ uint32_t phys128(uint32_t r, uint32_t c) {
    return r * 128 + ((c ^ (r & 7)) * 16);
}
__device__ __forceinline__ unsigned short hfu(float v) {
    return __half_as_ushort(__float2half_rn(v));
}

// ======================= mma.sync batched GEMM: BM=128, BN=128, BK=64, DEPTH=3 =======================
// C[M,N] = alpha*(A @ B^T) + bias. A:[M,K] half, B:[N,K] half row-major. K%64==0.
// OUT: 0=f32, 1=half, 2=relu half.
template<int OUT>
__global__ __launch_bounds__(256, 2)
void mma_gemm(const __half* __restrict__ A, const __half* __restrict__ B,
              const float* __restrict__ bias, char* __restrict__ Cptr,
              int K, int lda, int ldb, int ldc, float alpha)
{
    constexpr int DEPTH  = 3;
    constexpr int ABYTES = 128 * 128;
    constexpr int STAGE  = 2 * ABYTES;
    constexpr int NTL    = 8;

    extern __shared__ char sm[];
    const uint32_t smb = smem_u32(sm);

    const int tid = threadIdx.x;
    const int wid = tid >> 5, lane = tid & 31;
    const int wRow = (wid & 3) * 32;
    const int wCol = (wid >> 2) * 64;
    const int row0 = blockIdx.y * 128;
    const int col0 = blockIdx.x * 128;

    const __half* Ag[4]; const __half* Bg[4]; uint32_t Asm[4], Bsm[4];
#pragma unroll
    for (int i = 0; i < 4; i++) {
        int idx = tid + i * 256;
        int r = idx >> 3, c = idx & 7;
        Ag[i]  = A + (size_t)(row0 + r) * lda + c * 8;
        Bg[i]  = B + (size_t)(col0 + r) * ldb + c * 8;
        Asm[i] = phys128(r, c);
        Bsm[i] = ABYTES + phys128(r, c);
    }

    const uint32_t ra0 = (uint32_t)(wRow + (lane & 15)) * 128;
    const uint32_t rmA = (uint32_t)(lane & 15) & 7;
    const uint32_t sA  = lane >> 4;
    const uint32_t rb0 = (uint32_t)(wCol + ((lane >> 4) << 3) + (lane & 7)) * 128;
    const uint32_t rmB = (uint32_t)lane & 7;
    const uint32_t sB  = (lane >> 3) & 1;

    float acc[2][NTL][4];
#pragma unroll
    for (int i = 0; i < 2; i++)
#pragma unroll
        for (int j = 0; j < NTL; j++)
#pragma unroll
            for (int k = 0; k < 4; k++) acc[i][j][k] = 0.f;

    const int NC = K / 64;
    const int PRE = NC < (DEPTH - 1) ? NC : (DEPTH - 1);
    for (int s = 0; s < PRE; s++) {
#pragma unroll
        for (int i = 0; i < 4; i++) {
            CP_ASYNC(smb + s * STAGE + Asm[i], Ag[i] + s * 64);
            CP_ASYNC(smb + s * STAGE + Bsm[i], Bg[i] + s * 64);
        }
        CP_COMMIT();
    }
    int idx = PRE;
    int stC = 0, stL = PRE % DEPTH;
    for (int cch = 0; cch < NC; cch++) {
        const int rem = NC - 1 - cch;
        if (rem >= 1) { CP_WAIT(1); } else { CP_WAIT(0); }
        __syncthreads();
        if (idx < NC) {
#pragma unroll
            for (int i = 0; i < 4; i++) {
                CP_ASYNC(smb + stL * STAGE + Asm[i], Ag[i] + idx * 64);
                CP_ASYNC(smb + stL * STAGE + Bsm[i], Bg[i] + idx * 64);
            }
            CP_COMMIT();
            idx++;
            stL = (stL + 1 == DEPTH) ? 0 : stL + 1;
        }
        const uint32_t sb = smb + stC * STAGE;
        stC = (stC + 1 == DEPTH) ? 0 : stC + 1;
#pragma unroll
        for (int kk = 0; kk < 4; kk++) {
            const uint32_t cA = ((2 * kk + sA) ^ rmA) * 16;
            const uint32_t cB = ((2 * kk + sB) ^ rmB) * 16;
            uint32_t a[2][4], b[NTL][2];
#pragma unroll
            for (int mt = 0; mt < 2; mt++)
                LDSM_X4(a[mt][0], a[mt][1], a[mt][2], a[mt][3],
                        sb + ra0 + mt * 2048 + cA);
#pragma unroll
            for (int np = 0; np < 4; np++)
                LDSM_X4(b[2 * np][0], b[2 * np][1], b[2 * np + 1][0], b[2 * np + 1][1],
                        sb + ABYTES + rb0 + np * 2048 + cB);
#pragma unroll
            for (int mt = 0; mt < 2; mt++)
#pragma unroll
                for (int nt = 0; nt < NTL; nt++)
                    MMA_F16(acc[mt][nt], a[mt], b[nt]);
        }
    }

    const int gid = lane >> 2, t4 = lane & 3;
#pragma unroll
    for (int mt = 0; mt < 2; mt++) {
        const int r1 = row0 + wRow + mt * 16 + gid;
        const long long ro1 = (long long)r1 * ldc;
        const long long ro2 = ro1 + 8LL * ldc;
#pragma unroll
        for (int nt = 0; nt < NTL; nt++) {
            const int cc = col0 + wCol + nt * 8 + t4 * 2;
            const float b0 = bias ? bias[cc] : 0.f;
            const float b1 = bias ? bias[cc + 1] : 0.f;
            float v0 = acc[mt][nt][0] * alpha + b0;
            float v1 = acc[mt][nt][1] * alpha + b1;
            float v2 = acc[mt][nt][2] * alpha + b0;
            float v3 = acc[mt][nt][3] * alpha + b1;
            if constexpr (OUT == 0) {
                float* C = (float*)Cptr;
                *(float2*)(C + ro1 + cc) = make_float2(v0, v1);
                *(float2*)(C + ro2 + cc) = make_float2(v2, v3);
            } else {
                if constexpr (OUT == 2) {
                    v0 = fmaxf(v0, 0.f); v1 = fmaxf(v1, 0.f);
                    v2 = fmaxf(v2, 0.f); v3 = fmaxf(v3, 0.f);
                }
                __half* C = (__half*)Cptr;
                ushort2 o1, o2;
                o1.x = hfu(v0); o1.y = hfu(v1);
                o2.x = hfu(v2); o2.y = hfu(v3);
                *(ushort2*)(C + ro1 + cc) = o1;
                *(ushort2*)(C + ro2 + cc) = o2;
            }
        }
    }
}

// ======================= flash attention: 3-stage ring, ONE sync per iter =======================
__global__ __launch_bounds__(256, 2)
void flash_k(const __half* __restrict__ QKV, const int* __restrict__ mask,
             __half* __restrict__ CTX)
{
    constexpr int QLD   = 3 * DM;
    constexpr int CH128 = 8192;
    constexpr int CH64  = 4096;
    constexpr int QOFF  = 0;
    constexpr int ST0   = 16384;
    constexpr int VOFF  = 8192;
    constexpr int MOFF  = 16384;
    constexpr int STSZ  = 16640;
    constexpr int NJ    = SEQ / 64;
    constexpr float SCLL2E = 0.125f * 1.44269504f;

    extern __shared__ char sm[];
    const uint32_t smb = smem_u32(sm);

    const int tid = threadIdx.x;
    const int wid = tid >> 5, lane = tid & 31;
    const int gid = lane >> 2, t4 = lane & 3;
    const int qb = blockIdx.x, z = blockIdx.y;
    const int b = z >> 4, h = z & 15;

    const int rr = tid >> 2, cc4 = tid & 3;
    const size_t qrow0 = (size_t)(b * SEQ + qb * 128);
    const __half* Qg  = QKV + (qrow0 + rr) * QLD + h * DKH + cc4 * 8;
    const __half* Kg0 = QKV + ((size_t)b * SEQ + rr) * QLD + DM + h * DKH + cc4 * 8;
    const __half* Vg0 = QKV + ((size_t)b * SEQ + rr) * QLD + 2 * DM + h * DKH + cc4 * 8;
    const uint32_t physrc = phys(rr, cc4);

    auto issue_stage = [&](int jb, int st) {
        const uint32_t sb = smb + ST0 + st * STSZ;
        const __half* kgb = Kg0 + (size_t)jb * 64 * QLD;
#pragma unroll
        for (int kc = 0; kc < 2; kc++)
            CP_ASYNC(sb + kc * CH64 + physrc, kgb + kc * 32);
        const __half* vgb = Vg0 + (size_t)jb * 64 * QLD;
#pragma unroll
        for (int kc = 0; kc < 2; kc++)
            CP_ASYNC(sb + VOFF + kc * CH64 + physrc, vgb + kc * 32);
        if (tid < 16)
            CP_ASYNC(sb + MOFF + tid * 16, mask + (size_t)b * SEQ + jb * 64 + tid * 4);
    };

#pragma unroll
    for (int kc = 0; kc < 2; kc++)
#pragma unroll
        for (int it = 0; it < 2; it++)
            CP_ASYNC(smb + QOFF + kc * CH128 + physrc + it * 32 * 128,
                     Qg + (size_t)it * 64 * QLD + kc * 32);
    issue_stage(0, 0);
    CP_COMMIT();
    issue_stage(1, 1);
    CP_COMMIT();
    CP_WAIT(1);
    __syncthreads();

    uint32_t qa[4][4];
    {
        const uint32_t qbase0 = phys(lane & 15, (lane >> 4)) + wid * 1024;
        const uint32_t qbase1 = phys(lane & 15, 2 + (lane >> 4)) + wid * 1024;
#pragma unroll
        for (int kc = 0; kc < 2; kc++) {
            LDSM_X4(qa[kc * 2][0], qa[kc * 2][1], qa[kc * 2][2], qa[kc * 2][3],
                    smb + QOFF + kc * CH128 + qbase0);
            LDSM_X4(qa[kc * 2 + 1][0], qa[kc * 2 + 1][1], qa[kc * 2 + 1][2], qa[kc * 2 + 1][3],
                    smb + QOFF + kc * CH128 + qbase1);
        }
    }

    const uint32_t bb0 = phys(((lane >> 4) << 3) + (lane & 7), ((lane >> 3) & 1));
    const uint32_t bb1 = phys(((lane >> 4) << 3) + (lane & 7), 2 + ((lane >> 3) & 1));
    const uint32_t vtb0 = phys(lane & 15, (lane >> 4));
    const uint32_t vtb1 = phys(lane & 15, 2 + (lane >> 4));

    float O[8][4];
#pragma unroll
    for (int i = 0; i < 8; i++)
#pragma unroll
        for (int j = 0; j < 4; j++) O[i][j] = 0.f;
    float l0 = 0.f, l1 = 0.f;

    int bufC = 0, bufL = 2;       // compute buffer, load buffer (= (j+2)%3)
    for (int j = 0; j < NJ; j++) {
        const uint32_t sb = smb + ST0 + bufC * STSZ;
        const int* msm = (const int*)(sm + ST0 + bufC * STSZ + MOFF);

        float s[8][4];
#pragma unroll
        for (int i = 0; i < 8; i++)
#pragma unroll
            for (int k = 0; k < 4; k++) s[i][k] = 0.f;
#pragma unroll
        for (int kidx = 0; kidx < 4; kidx++) {
            const uint32_t cb = sb + (kidx >> 1) * CH64 + ((kidx & 1) ? bb1 : bb0);
#pragma unroll
            for (int np = 0; np < 4; np++) {
                uint32_t r0, r1, r2, r3;
                LDSM_X4(r0, r1, r2, r3, cb + np * 1024);
                uint32_t p0[2] = {r0, r1}, p1[2] = {r2, r3};
                MMA_F16(s[2 * np], qa[kidx], p0);
                MMA_F16(s[2 * np + 1], qa[kidx], p1);
            }
        }

        // prefetch stage j+2 into ring slot consumed at iteration j-1 (safe: all
        // threads passed the previous barrier, hence finished reading it)
        if (j + 2 < NJ) { issue_stage(j + 2, bufL); CP_COMMIT(); }

        float sum0 = 0.f, sum1 = 0.f;
#pragma unroll
        for (int nt = 0; nt < 8; nt++) {
            const int c0 = nt * 8 + t4 * 2;
            const float a0 = msm[c0] ? 0.f : -1.0e9f;
            const float a1 = msm[c0 + 1] ? 0.f : -1.0e9f;
            s[nt][0] = exp2f(fmaf(s[nt][0], SCLL2E, a0));
            s[nt][1] = exp2f(fmaf(s[nt][1], SCLL2E, a1));
            s[nt][2] = exp2f(fmaf(s[nt][2], SCLL2E, a0));
            s[nt][3] = exp2f(fmaf(s[nt][3], SCLL2E, a1));
            sum0 += s[nt][0] + s[nt][1];
            sum1 += s[nt][2] + s[nt][3];
        }
        sum0 += __shfl_xor_sync(0xffffffffu, sum0, 1);
        sum0 += __shfl_xor_sync(0xffffffffu, sum0, 2);
        sum1 += __shfl_xor_sync(0xffffffffu, sum1, 1);
        sum1 += __shfl_xor_sync(0xffffffffu, sum1, 2);
        l0 += sum0;
        l1 += sum1;

#pragma unroll
        for (int kt = 0; kt < 4; kt++) {
            uint32_t pa[4];
            PACK_F16X2(pa[0], s[2 * kt][0], s[2 * kt][1]);
            PACK_F16X2(pa[1], s[2 * kt][2], s[2 * kt][3]);
            PACK_F16X2(pa[2], s[2 * kt + 1][0], s[2 * kt + 1][1]);
            PACK_F16X2(pa[3], s[2 * kt + 1][2], s[2 * kt + 1][3]);
#pragma unroll
            for (int np = 0; np < 4; np++) {
                uint32_t r0, r1, r2, r3;
                LDSM_X4_T(r0, r1, r2, r3,
                          sb + VOFF + (np >> 1) * CH64 + ((np & 1) ? vtb1 : vtb0) + kt * 1024);
                uint32_t p0[2] = {r0, r1}, p1[2] = {r2, r3};
                MMA_F16(O[2 * np], pa, p0);
                MMA_F16(O[2 * np + 1], pa, p1);
            }
        }

        // single barrier per iteration: wait next stage's data, make it visible
        if (j + 1 < NJ) {
            if (j + 2 < NJ) { CP_WAIT(1); } else { CP_WAIT(0); }
            __syncthreads();
        }
        bufC = (bufC + 1 == 3) ? 0 : bufC + 1;
        bufL = (bufL + 1 == 3) ? 0 : bufL + 1;
    }

    const float inv0 = 1.f / l0, inv1 = 1.f / l1;
    const int q0 = qb * 128 + wid * 16 + gid;
    __half* C1 = CTX + ((size_t)(b * SEQ + q0)) * DM + h * DKH;
    __half* C2 = C1 + 8 * DM;
#pragma unroll
    for (int nt = 0; nt < 8; nt++) {
        const int cc = nt * 8 + t4 * 2;
        ushort2 o1, o2;
        o1.x = hfu(O[nt][0] * inv0); o1.y = hfu(O[nt][1] * inv0);
        o2.x = hfu(O[nt][2] * inv1); o2.y = hfu(O[nt][3] * inv1);
        *(ushort2*)(C1 + cc) = o1;
        *(ushort2*)(C2 + cc) = o2;
    }
}

// ======================= unified prologue =======================
__global__ void prep_all_k(const float* __restrict__ Wq, const float* __restrict__ Wk,
                           const float* __restrict__ Wv, const float* __restrict__ Wo,
                           const float* __restrict__ W1, const float* __restrict__ W2,
                           __half* __restrict__ WQKVT, __half* __restrict__ WOT,
                           __half* __restrict__ W1T, __half* __restrict__ W2T,
                           const float* __restrict__ bq, const float* __restrict__ bk,
                           const float* __restrict__ bv, float* __restrict__ BQKV,
                           const float* __restrict__ x, __half* __restrict__ XH)
{
    __shared__ float t[32][33];
    const int idx = blockIdx.x;
    const int tx = threadIdx.x, ty = threadIdx.y;
    const int lt = ty * 32 + tx;

    if (idx >= 12288) {
        const size_t off = ((size_t)(idx - 12288) * 1024) + (size_t)lt * 4;
        float4 v = *(const float4*)(x + off);
        ushort4 o;
        o.x = hfu(v.x); o.y = hfu(v.y); o.z = hfu(v.z); o.w = hfu(v.w);
        *(ushort4*)(XH + off) = o;
        return;
    }

    if (idx == 0) {
        for (int i = lt; i < DM; i += 256) {
            BQKV[i] = bq[i];
            BQKV[i + DM] = bk[i];
            BQKV[i + 2 * DM] = bv[i];
        }
    }

    const float* in;
    __half* out;
    int K, N, n0, k0;
    if (idx < 4096) {
        const int w = idx >> 10, tile = idx & 1023;
        in = (w == 0) ? Wq : (w == 1) ? Wk : (w == 2) ? Wv : Wo;
        out = (w == 3) ? WOT : WQKVT + (size_t)w * DM * DM;
        K = DM; N = DM;
        n0 = (tile & 31) * 32; k0 = (tile >> 5) * 32;
    } else if (idx < 8192) {
        const int tile = idx - 4096;
        in = W1; out = W1T; K = DM; N = DFF;
        n0 = (tile & 127) * 32; k0 = (tile >> 7) * 32;
    } else {
        const int tile = idx - 8192;
        in = W2; out = W2T; K = DFF; N = DM;
        n0 = (tile & 31) * 32; k0 = (tile >> 5) * 32;
    }

    for (int j = ty; j < 32; j += 8) t[j][tx] = in[(size_t)(k0 + j) * N + n0 + tx];
    __syncthreads();
    for (int j = ty; j < 32; j += 8)
        out[(size_t)(n0 + j) * K + k0 + tx] = __float2half_rn(t[tx][j]);
}

// ======================= reductions / LN =======================
__device__ __forceinline__ float blkSum(float v, float* red)
{
#pragma unroll
    for (int o = 16; o > 0; o >>= 1) v += __shfl_xor_sync(0xffffffffu, v, o);
    int w = threadIdx.x >> 5, l = threadIdx.x & 31;
    if (l == 0) red[w] = v;
    __syncthreads();
    if (threadIdx.x < 8) {
        v = red[threadIdx.x];
#pragma unroll
        for (int o = 4; o > 0; o >>= 1) v += __shfl_xor_sync(0xffu, v, o);
        if (threadIdx.x == 0) red[0] = v;
    }
    __syncthreads();
    float r = red[0];
    __syncthreads();
    return r;
}

template<bool EMIT_H>
__global__ void addln_k(const float* __restrict__ a, const float* __restrict__ bres,
                        const float* __restrict__ g, const float* __restrict__ be,
                        float* __restrict__ out, __half* __restrict__ outh)
{
    __shared__ float red[32];
    const long long row = blockIdx.x;
    const float* pa = a + row * DM;
    const float* pb = bres + row * DM;
    const int tid = threadIdx.x;
    float v[4], s = 0.f, s2 = 0.f;
    {
        float4 xa = *(const float4*)(pa + tid * 4);
        float4 xb = *(const float4*)(pb + tid * 4);
        v[0] = xa.x + xb.x; v[1] = xa.y + xb.y;
        v[2] = xa.z + xb.z; v[3] = xa.w + xb.w;
#pragma unroll
        for (int j = 0; j < 4; j++) { s += v[j]; s2 += v[j] * v[j]; }
    }
    s = blkSum(s, red);
    s2 = blkSum(s2, red);
    float mu = s * (1.f / DM);
    float var = s2 * (1.f / DM) - mu * mu;
    float inv = rsqrtf(var + 1e-5f);
    float4 gv = *(const float4*)(g + tid * 4);
    float4 bv = *(const float4*)(be + tid * 4);
    float o0 = (v[0] - mu) * inv * gv.x + bv.x;
    float o1 = (v[1] - mu) * inv * gv.y + bv.y;
    float o2 = (v[2] - mu) * inv * gv.z + bv.z;
    float o3 = (v[3] - mu) * inv * gv.w + bv.w;
    *(float4*)(out + row * DM + tid * 4) = make_float4(o0, o1, o2, o3);
    if (EMIT_H) {
        ushort4 oh;
        oh.x = hfu(o0); oh.y = hfu(o1); oh.z = hfu(o2); oh.w = hfu(o3);
        *(ushort4*)(outh + row * DM + tid * 4) = oh;
    }
}

// ======================= launch =======================
extern "C" void kernel_launch(void* const* d_in, const int* in_sizes, int n_in,
                              void* d_out, int out_size)
{
    const float* x    = (const float*)d_in[0];
    const int*   mask = (const int*)  d_in[1];
    const float* Wq = (const float*)d_in[2];  const float* bq = (const float*)d_in[3];
    const float* Wk = (const float*)d_in[4];  const float* bk = (const float*)d_in[5];
    const float* Wv = (const float*)d_in[6];  const float* bv = (const float*)d_in[7];
    const float* Wo = (const float*)d_in[8];  const float* bo = (const float*)d_in[9];
    const float* W1 = (const float*)d_in[10]; const float* b1 = (const float*)d_in[11];
    const float* W2 = (const float*)d_in[12]; const float* b2 = (const float*)d_in[13];
    const float* g1 = (const float*)d_in[14]; const float* be1 = (const float*)d_in[15];
    const float* g2 = (const float*)d_in[16]; const float* be2 = (const float*)d_in[17];
    float* out = (float*)d_out;

    float *TMP, *H, *BQKV;
    __half *XH, *QKV, *CTX, *WQKVT, *WOT, *W1T, *W2T, *HH, *FF;
    cudaGetSymbolAddress((void**)&TMP, g_tmp);
    cudaGetSymbolAddress((void**)&H, g_h);
    cudaGetSymbolAddress((void**)&XH, g_xh);
    cudaGetSymbolAddress((void**)&QKV, g_qkv);
    cudaGetSymbolAddress((void**)&CTX, g_ctx);
    cudaGetSymbolAddress((void**)&WQKVT, g_WqkvT);
    cudaGetSymbolAddress((void**)&WOT, g_WoT);
    cudaGetSymbolAddress((void**)&W1T, g_W1T);
    cudaGetSymbolAddress((void**)&W2T, g_W2T);
    cudaGetSymbolAddress((void**)&HH, g_hh);
    cudaGetSymbolAddress((void**)&FF, g_ff);
    cudaGetSymbolAddress((void**)&BQKV, g_bqkv);

    const int SMGM = 3 * 32 * 1024;           // 98304
    const int SMFL = 16384 + 3 * 16640;       // 66304
    cudaFuncSetAttribute(mma_gemm<0>, cudaFuncAttributeMaxDynamicSharedMemorySize, SMGM);
    cudaFuncSetAttribute(mma_gemm<1>, cudaFuncAttributeMaxDynamicSharedMemorySize, SMGM);
    cudaFuncSetAttribute(mma_gemm<2>, cudaFuncAttributeMaxDynamicSharedMemorySize, SMGM);
    cudaFuncSetAttribute(flash_k, cudaFuncAttributeMaxDynamicSharedMemorySize, SMFL);

    const dim3 t32(32, 8);

    // launch 1: unified prologue (weights + biases + x->half)
    prep_all_k<<<16384, t32>>>(Wq, Wk, Wv, Wo, W1, W2, WQKVT, WOT, W1T, W2T,
                               bq, bk, bv, BQKV, x, XH);
    // launch 2: fused QKV projection
    {
        dim3 g(3 * DM / 128, NT / 128, 1);
        mma_gemm<1><<<g, 256, SMGM>>>(XH, WQKVT, BQKV, (char*)QKV, DM, DM, DM, 3 * DM, 1.f);
    }
    // launch 3: flash attention
    flash_k<<<dim3(SEQ / 128, 64), 256, SMFL>>>(QKV, mask, CTX);
    // launch 4: attn_out = ctx @ Wo + bo
    {
        dim3 g(DM / 128, NT / 128, 1);
        mma_gemm<0><<<g, 256, SMGM>>>(CTX, WOT, bo, (char*)TMP, DM, DM, DM, DM, 1.f);
    }
    // launch 5: LN1
    addln_k<true><<<NT, 256>>>(x, TMP, g1, be1, H, HH);
    // launch 6: FFN1
    {
        dim3 g(DFF / 128, NT / 128, 1);
        mma_gemm<2><<<g, 256, SMGM>>>(HH, W1T, b1, (char*)FF, DM, DM, DM, DFF, 1.f);
    }
    // launch 7: FFN2
    {
        dim3 g(DM / 128, NT / 128, 1);
        mma_gemm<0><<<g, 256, SMGM>>>(FF, W2T, b2, (char*)TMP, DFF, DFF, DFF, DM, 1.f);
    }
    // launch 8: LN2
    addln_k<false><<<NT, 256>>>(H, TMP, g2, be2, out, nullptr);
}